// round 13
// baseline (speedup 1.0000x reference)
#include <cuda_runtime.h>
#include <cuda_bf16.h>
#include <cstdint>

// Problem constants
#define BB 8
#define CC 256
#define HH 112
#define HWSZ 12544              // 112*112
#define ELEMS_PER_IMG (CC * HWSZ)
#define TOTAL_ELEMS (BB * ELEMS_PER_IMG)

// Scratch (device globals; no allocations allowed)
__device__ __nv_bfloat16 g_Q[TOTAL_ELEMS];
__device__ __nv_bfloat16 g_K[TOTAL_ELEMS];
__device__ __nv_bfloat16 g_V[TOTAL_ELEMS];
__device__ __nv_bfloat16 g_Zs[TOTAL_ELEMS];

__device__ __forceinline__ uint32_t smem_u32(const void* p) {
    uint32_t a;
    asm("{ .reg .u64 t; cvta.to.shared.u64 t, %1; cvt.u32.u64 %0, t; }"
        : "=r"(a) : "l"(p));
    return a;
}
// pack two floats into bf16x2: lo -> low half, hi -> high half
__device__ __forceinline__ uint32_t pack_bf16(float lo, float hi) {
    uint32_t r;
    asm("cvt.rn.bf16x2.f32 %0, %1, %2;" : "=r"(r) : "f"(hi), "f"(lo));
    return r;
}
// ldmatrix x4 (normal): 4 8x8 b16 tiles; lanes 0-7/8-15/16-23/24-31 give row
// addresses of matrices 0..3; reg i = matrix i.
__device__ __forceinline__ void ldsm_x4(uint32_t* r, uint32_t addr) {
    asm volatile("ldmatrix.sync.aligned.m8n8.x4.shared.b16 {%0,%1,%2,%3}, [%4];"
        : "=r"(r[0]), "=r"(r[1]), "=r"(r[2]), "=r"(r[3]) : "r"(addr));
}
// ldmatrix x4 transposed: source tiles are [k][n]; frag comes out as-if [n][k].
__device__ __forceinline__ void ldsm_x4_t(uint32_t* r, uint32_t addr) {
    asm volatile("ldmatrix.sync.aligned.m8n8.x4.trans.shared.b16 {%0,%1,%2,%3}, [%4];"
        : "=r"(r[0]), "=r"(r[1]), "=r"(r[2]), "=r"(r[3]) : "r"(addr));
}
// mma.sync m16n8k16 bf16 (baseline PTX; fragment layout validated R9-R12)
__device__ __forceinline__ void mma_bf16(float* c, const uint32_t* a, const uint32_t* b) {
    asm volatile(
        "mma.sync.aligned.m16n8k16.row.col.f32.bf16.bf16.f32 "
        "{%0,%1,%2,%3}, {%4,%5,%6,%7}, {%8,%9}, {%0,%1,%2,%3};"
        : "+f"(c[0]), "+f"(c[1]), "+f"(c[2]), "+f"(c[3])
        : "r"(a[0]), "r"(a[1]), "r"(a[2]), "r"(a[3]), "r"(b[0]), "r"(b[1]));
}

// ============================================================================
// bf16 tensor-core GEMM: out = W @ in (+res+relu if float out)
// CTA 128x128, 256 threads (8 warps 2x4), warp tile 64x32.
// A smem [m][k] pitch 36 words (normal ldsm); B smem [k][n] NATURAL layout,
// pitch 68 words (272B -> trans-ldsm conflict-free), staged with contiguous
// 128-bit global loads (fp32 inputs) or raw uint4 copies (bf16 input).
// ============================================================================
#define PAB 36
#define PBW 68
#define ATILE_W (128 * PAB)                  // 4608 words
#define BTILE_W (32 * PBW)                   // 2176 words
#define STG_W (ATILE_W + BTILE_W)            // 6784 words
#define GEMM_SMEM (2 * STG_W * 4)            // 54272 B

__global__ void __launch_bounds__(256, 2)
gemm_tc_kernel(const float* __restrict__ Wmat,
               const void* __restrict__ inp,
               const float* __restrict__ res,
               void* __restrict__ outp,
               int in_bf16, int out_bf16, int do_relu)
{
    extern __shared__ uint32_t smu[];
    const uint32_t smb = smem_u32(smu);
    uint32_t* Abuf[2] = { smu,           smu + STG_W };
    uint32_t* Bbuf[2] = { smu + ATILE_W, smu + STG_W + ATILE_W };
    const uint32_t abase[2] = { smb,                 smb + STG_W * 4 };
    const uint32_t bbase[2] = { smb + ATILE_W * 4,   smb + (STG_W + ATILE_W) * 4 };

    const int tid  = threadIdx.x;
    const int wid  = tid >> 5;
    const int lane = tid & 31;
    const int g    = lane >> 2;
    const int t    = lane & 3;
    const int wm   = (wid >> 2) * 64;        // 0 or 64
    const int wn   = (wid & 3) * 32;

    const int m0 = blockIdx.x * 128;
    const int n0 = blockIdx.y * 128;
    const int b  = blockIdx.z;
    const float*    inf = (const float*)inp + (size_t)b * ELEMS_PER_IMG;
    const uint32_t* inw = (const uint32_t*)inp + (size_t)b * (ELEMS_PER_IMG / 2);

    // fragment lane offsets (bytes within a stage)
    const uint32_t aoff = ((wm + (lane & 15)) * PAB + ((lane >> 4) << 2)) * 4;
    const uint32_t boff = ((((lane & 7) + ((lane >> 3) & 1) * 8) * PBW)
                           + ((lane >> 4) << 2)) * 4;

    // A staging: thread owns (rr, q0),(rr, q1); quad q covers k=q*8..q*8+7
    const int rr = tid & 127;
    const int q0 = tid >> 7;
    const int q1 = q0 + 2;

    float acc[4][4][4];
#pragma unroll
    for (int f = 0; f < 4; f++)
#pragma unroll
        for (int j = 0; j < 4; j++)
#pragma unroll
            for (int e = 0; e < 4; e++) acc[f][j][e] = 0.0f;

    uint32_t pa[2][4];
    uint32_t pbf[4][2];     // fp32-input path: 4 slots x 2 packed words
    uint4    pbq[2];        // bf16-input path: 2 slots x uint4

    auto load_chunk = [&](int kk) {
#pragma unroll
        for (int it = 0; it < 2; ++it) {
            const int q  = it ? q1 : q0;
            const int kb = kk + q * 8;
            const float* arow = &Wmat[(m0 + rr) * CC + kb];
            float4 a0 = *reinterpret_cast<const float4*>(arow);
            float4 a1 = *reinterpret_cast<const float4*>(arow + 4);
            pa[it][0] = pack_bf16(a0.x, a0.y);
            pa[it][1] = pack_bf16(a0.z, a0.w);
            pa[it][2] = pack_bf16(a1.x, a1.y);
            pa[it][3] = pack_bf16(a1.z, a1.w);
        }
        if (in_bf16) {
#pragma unroll
            for (int it = 0; it < 2; ++it) {
                const int f = tid + it * 256;
                const int k = f >> 4, n8 = f & 15;
                pbq[it] = *reinterpret_cast<const uint4*>(
                    &inw[(size_t)(kk + k) * (HWSZ / 2) + (n0 >> 1) + n8 * 4]);
            }
        } else {
#pragma unroll
            for (int it = 0; it < 4; ++it) {
                const int f = tid + it * 256;
                const int k = f >> 5, n4 = f & 31;
                float4 v = *reinterpret_cast<const float4*>(
                    &inf[(size_t)(kk + k) * HWSZ + n0 + n4 * 4]);
                pbf[it][0] = pack_bf16(v.x, v.y);
                pbf[it][1] = pack_bf16(v.z, v.w);
            }
        }
    };
    auto store_chunk = [&](int p) {
#pragma unroll
        for (int it = 0; it < 2; ++it) {
            const int q = it ? q1 : q0;
            *reinterpret_cast<uint4*>(&Abuf[p][rr * PAB + q * 4]) =
                *reinterpret_cast<uint4*>(pa[it]);
        }
        if (in_bf16) {
#pragma unroll
            for (int it = 0; it < 2; ++it) {
                const int f = tid + it * 256;
                const int k = f >> 4, n8 = f & 15;
                *reinterpret_cast<uint4*>(&Bbuf[p][k * PBW + n8 * 4]) = pbq[it];
            }
        } else {
#pragma unroll
            for (int it = 0; it < 4; ++it) {
                const int f = tid + it * 256;
                const int k = f >> 5, n4 = f & 31;
                *reinterpret_cast<uint2*>(&Bbuf[p][k * PBW + n4 * 2]) =
                    *reinterpret_cast<uint2*>(pbf[it]);
            }
        }
    };

    load_chunk(0);
    store_chunk(0);
    __syncthreads();

    for (int i = 0; i < 8; ++i) {
        const int p = i & 1;

        if (i < 7) load_chunk((i + 1) * 32);   // prefetch into regs

        const uint32_t aA = abase[p] + aoff;
        const uint32_t aB = bbase[p] + boff + (wn >> 1) * 4;
#pragma unroll
        for (int ks = 0; ks < 2; ++ks) {
            uint32_t afr[4][4];
#pragma unroll
            for (int f = 0; f < 4; ++f)
                ldsm_x4(afr[f], aA + f * (16 * PAB * 4) + ks * 32);
#pragma unroll
            for (int j2 = 0; j2 < 2; ++j2) {
                uint32_t bfr[4];
                ldsm_x4_t(bfr, aB + j2 * 32 + ks * (16 * PBW * 4));
#pragma unroll
                for (int f = 0; f < 4; ++f) {
                    mma_bf16(acc[f][2 * j2],     afr[f], bfr);
                    mma_bf16(acc[f][2 * j2 + 1], afr[f], bfr + 2);
                }
            }
        }

        if (i < 7) store_chunk(p ^ 1);
        __syncthreads();
    }

    // ---- epilogue ----
    if (out_bf16) {
        uint32_t* ob = reinterpret_cast<uint32_t*>(outp) + (size_t)b * (ELEMS_PER_IMG / 2);
#pragma unroll
        for (int f = 0; f < 4; ++f) {
#pragma unroll
            for (int j = 0; j < 4; ++j) {
                const int row = m0 + wm + f * 16 + g;
                const int col = n0 + wn + j * 8 + 2 * t;   // even
                ob[((size_t)row * HWSZ + col) >> 1]       = pack_bf16(acc[f][j][0], acc[f][j][1]);
                ob[((size_t)(row + 8) * HWSZ + col) >> 1] = pack_bf16(acc[f][j][2], acc[f][j][3]);
            }
        }
    } else {
        float* outb = reinterpret_cast<float*>(outp) + (size_t)b * ELEMS_PER_IMG;
        const float* resb = res ? res + (size_t)b * ELEMS_PER_IMG : nullptr;
#pragma unroll
        for (int f = 0; f < 4; ++f) {
#pragma unroll
            for (int j = 0; j < 4; ++j) {
                const int row = m0 + wm + f * 16 + g;
                const int col = n0 + wn + j * 8 + 2 * t;
                float2 v0 = { acc[f][j][0], acc[f][j][1] };
                float2 v1 = { acc[f][j][2], acc[f][j][3] };
                if (do_relu) {
                    float2 r0 = *reinterpret_cast<const float2*>(&resb[(size_t)row * HWSZ + col]);
                    float2 r1 = *reinterpret_cast<const float2*>(&resb[(size_t)(row + 8) * HWSZ + col]);
                    v0.x = fmaxf(v0.x + r0.x, 0.0f);
                    v0.y = fmaxf(v0.y + r0.y, 0.0f);
                    v1.x = fmaxf(v1.x + r1.x, 0.0f);
                    v1.y = fmaxf(v1.y + r1.y, 0.0f);
                }
                *reinterpret_cast<float2*>(&outb[(size_t)row * HWSZ + col]) = v0;
                *reinterpret_cast<float2*>(&outb[(size_t)(row + 8) * HWSZ + col]) = v1;
            }
        }
    }
}

// ============================================================================
// bf16 tensor-core attention per (b,c): natural-layout staging everywhere.
// Q/M: [i][k] pitch 60 (normal ldsm). K,V: [k][j] pitch 60 (trans ldsm).
// 224 threads = 7 warps; warp w owns rows 16w..16w+15. Z written as bf16.
// ============================================================================
#define PTQ 60
#define ATSZ (HH * PTQ)                 // 6720 words
#define ATTN_SMEM (3 * ATSZ * 4)        // 80640 B

__global__ void __launch_bounds__(224, 2)
attn_tc_kernel(const uint32_t* __restrict__ Qg, const uint32_t* __restrict__ Kg,
               const uint32_t* __restrict__ Vg, uint32_t* __restrict__ Z)
{
    extern __shared__ uint32_t smu[];
    const uint32_t smb = smem_u32(smu);
    uint32_t* Ks = smu;
    uint32_t* Vs = smu + ATSZ;
    uint32_t* Ms = smu + 2 * ATSZ;
    const uint32_t kbase = smb;
    const uint32_t vbase = smb + ATSZ * 4;
    const uint32_t mbase = smb + 2 * ATSZ * 4;

    const size_t wbase = (size_t)blockIdx.x * (HWSZ / 2);
    const int tid  = threadIdx.x;
    const int wid  = tid >> 5;
    const int lane = tid & 31;
    const int g    = lane >> 2;
    const int t    = lane & 3;
    const int r0   = wid * 16;

    const uint32_t* Qb = Qg + wbase;
    const uint32_t* Kb = Kg + wbase;
    const uint32_t* Vb = Vg + wbase;

    // straight copies into pitch-60 natural layouts
    for (int i = tid; i < HWSZ / 2; i += 224) {
        const int row = i / 56, jp = i % 56;
        const int o = row * PTQ + jp;
        Ms[o] = Qb[i];
        Ks[o] = Kb[i];
        Vs[o] = Vb[i];
    }
    __syncthreads();

    const uint32_t aoff = ((r0 + (lane & 15)) * PTQ + ((lane >> 4) << 2)) * 4;
    const uint32_t boff = ((((lane & 7) + ((lane >> 3) & 1) * 8) * PTQ)
                           + ((lane >> 4) << 2)) * 4;

    float acc[14][4];
#pragma unroll
    for (int j = 0; j < 14; j++)
#pragma unroll
        for (int e = 0; e < 4; e++) acc[j][e] = 0.0f;

    // ---- S = Q @ K (7 k16 steps; K via trans-ldsm from [k][j]) ----
#pragma unroll
    for (int ks = 0; ks < 7; ++ks) {
        uint32_t a[4];
        ldsm_x4(a, mbase + aoff + ks * 32);
#pragma unroll
        for (int j2 = 0; j2 < 7; ++j2) {
            uint32_t bfr[4];
            ldsm_x4_t(bfr, kbase + boff + j2 * 32 + ks * (16 * PTQ * 4));
            mma_bf16(acc[2 * j2],     a, bfr);
            mma_bf16(acc[2 * j2 + 1], a, bfr + 2);
        }
    }

    // ---- softmax ----
    {
        float mx0 = -1e30f, mx1 = -1e30f;
#pragma unroll
        for (int j = 0; j < 14; ++j) {
            mx0 = fmaxf(mx0, fmaxf(acc[j][0], acc[j][1]));
            mx1 = fmaxf(mx1, fmaxf(acc[j][2], acc[j][3]));
        }
        mx0 = fmaxf(mx0, __shfl_xor_sync(0xffffffffu, mx0, 1));
        mx0 = fmaxf(mx0, __shfl_xor_sync(0xffffffffu, mx0, 2));
        mx1 = fmaxf(mx1, __shfl_xor_sync(0xffffffffu, mx1, 1));
        mx1 = fmaxf(mx1, __shfl_xor_sync(0xffffffffu, mx1, 2));
        float s0 = 0.0f, s1 = 0.0f;
#pragma unroll
        for (int j = 0; j < 14; ++j) {
            acc[j][0] = __expf(acc[j][0] - mx0);
            acc[j][1] = __expf(acc[j][1] - mx0);
            acc[j][2] = __expf(acc[j][2] - mx1);
            acc[j][3] = __expf(acc[j][3] - mx1);
            s0 += acc[j][0] + acc[j][1];
            s1 += acc[j][2] + acc[j][3];
        }
        s0 += __shfl_xor_sync(0xffffffffu, s0, 1);
        s0 += __shfl_xor_sync(0xffffffffu, s0, 2);
        s1 += __shfl_xor_sync(0xffffffffu, s1, 1);
        s1 += __shfl_xor_sync(0xffffffffu, s1, 2);
        const float i0 = 1.0f / s0, i1 = 1.0f / s1;
#pragma unroll
        for (int j = 0; j < 14; ++j) {
            acc[j][0] *= i0; acc[j][1] *= i0;
            acc[j][2] *= i1; acc[j][3] *= i1;
        }
    }

    // ---- write M (bf16, contiguous words) into Ms; rows warp-private ----
    __syncwarp();
#pragma unroll
    for (int j = 0; j < 14; ++j) {
        Ms[(r0 + g) * PTQ + j * 4 + t]     = pack_bf16(acc[j][0], acc[j][1]);
        Ms[(r0 + g + 8) * PTQ + j * 4 + t] = pack_bf16(acc[j][2], acc[j][3]);
    }
    __syncwarp();

    // ---- Z = M @ V ----
#pragma unroll
    for (int j = 0; j < 14; j++)
#pragma unroll
        for (int e = 0; e < 4; e++) acc[j][e] = 0.0f;

#pragma unroll
    for (int ks = 0; ks < 7; ++ks) {
        uint32_t a[4];
        ldsm_x4(a, mbase + aoff + ks * 32);
#pragma unroll
        for (int j2 = 0; j2 < 7; ++j2) {
            uint32_t bfr[4];
            ldsm_x4_t(bfr, vbase + boff + j2 * 32 + ks * (16 * PTQ * 4));
            mma_bf16(acc[2 * j2],     a, bfr);
            mma_bf16(acc[2 * j2 + 1], a, bfr + 2);
        }
    }

    // ---- store Z as packed bf16 words ----
    uint32_t* Zb = Z + wbase;
#pragma unroll
    for (int j = 0; j < 14; ++j) {
        const int col = j * 8 + 2 * t;   // even
        Zb[((r0 + g) * HH + col) >> 1]     = pack_bf16(acc[j][0], acc[j][1]);
        Zb[((r0 + g + 8) * HH + col) >> 1] = pack_bf16(acc[j][2], acc[j][3]);
    }
}

extern "C" void kernel_launch(void* const* d_in, const int* in_sizes, int n_in,
                              void* d_out, int out_size)
{
    const float* x  = (const float*)d_in[0];
    const float* y  = (const float*)d_in[1];
    const float* WQ = (const float*)d_in[2];
    const float* WK = (const float*)d_in[3];
    const float* WV = (const float*)d_in[4];
    const float* WZ = (const float*)d_in[5];
    float* out = (float*)d_out;

    void *dQ, *dK, *dV, *dZ;
    cudaGetSymbolAddress(&dQ, g_Q);
    cudaGetSymbolAddress(&dK, g_K);
    cudaGetSymbolAddress(&dV, g_V);
    cudaGetSymbolAddress(&dZ, g_Zs);

    cudaFuncSetAttribute(attn_tc_kernel, cudaFuncAttributeMaxDynamicSharedMemorySize,
                         ATTN_SMEM);
    cudaFuncSetAttribute(gemm_tc_kernel, cudaFuncAttributeMaxDynamicSharedMemorySize,
                         GEMM_SMEM);

    dim3 gg(2, HWSZ / 128, BB);   // m-tile fastest -> B-tile L2 reuse

    gemm_tc_kernel<<<gg, 256, GEMM_SMEM>>>(WQ, x, nullptr, dQ, 0, 1, 0);
    gemm_tc_kernel<<<gg, 256, GEMM_SMEM>>>(WK, y, nullptr, dK, 0, 1, 0);
    gemm_tc_kernel<<<gg, 256, GEMM_SMEM>>>(WV, y, nullptr, dV, 0, 1, 0);
    attn_tc_kernel<<<BB * CC, 224, ATTN_SMEM>>>((const uint32_t*)dQ,
                                                (const uint32_t*)dK,
                                                (const uint32_t*)dV,
                                                (uint32_t*)dZ);
    gemm_tc_kernel<<<gg, 256, GEMM_SMEM>>>(WZ, dZ, x, out, 1, 0, 1);
}

// round 14
// speedup vs baseline: 1.2981x; 1.2981x over previous
#include <cuda_runtime.h>
#include <cuda_bf16.h>
#include <cstdint>

// Problem constants
#define BB 8
#define CC 256
#define HH 112
#define HWSZ 12544              // 112*112
#define ELEMS_PER_IMG (CC * HWSZ)
#define TOTAL_ELEMS (BB * ELEMS_PER_IMG)

// Scratch (device globals; no allocations allowed)
__device__ __nv_bfloat16 g_Q[TOTAL_ELEMS];
__device__ __nv_bfloat16 g_K[TOTAL_ELEMS];
__device__ __nv_bfloat16 g_V[TOTAL_ELEMS];
__device__ __nv_bfloat16 g_Zs[TOTAL_ELEMS];

__device__ __forceinline__ uint32_t smem_u32(const void* p) {
    uint32_t a;
    asm("{ .reg .u64 t; cvta.to.shared.u64 t, %1; cvt.u32.u64 %0, t; }"
        : "=r"(a) : "l"(p));
    return a;
}
// pack two floats into bf16x2: lo -> low half, hi -> high half
__device__ __forceinline__ uint32_t pack_bf16(float lo, float hi) {
    uint32_t r;
    asm("cvt.rn.bf16x2.f32 %0, %1, %2;" : "=r"(r) : "f"(hi), "f"(lo));
    return r;
}
// ldmatrix x4 (normal): 4 8x8 b16 tiles; lanes 0-7/8-15/16-23/24-31 give row
// addresses of matrices 0..3; reg i = matrix i.
__device__ __forceinline__ void ldsm_x4(uint32_t* r, uint32_t addr) {
    asm volatile("ldmatrix.sync.aligned.m8n8.x4.shared.b16 {%0,%1,%2,%3}, [%4];"
        : "=r"(r[0]), "=r"(r[1]), "=r"(r[2]), "=r"(r[3]) : "r"(addr));
}
// ldmatrix x4 transposed: source tiles are [k][n]; frag comes out as-if [n][k].
__device__ __forceinline__ void ldsm_x4_t(uint32_t* r, uint32_t addr) {
    asm volatile("ldmatrix.sync.aligned.m8n8.x4.trans.shared.b16 {%0,%1,%2,%3}, [%4];"
        : "=r"(r[0]), "=r"(r[1]), "=r"(r[2]), "=r"(r[3]) : "r"(addr));
}
// mma.sync m16n8k16 bf16 (baseline PTX; fragment layout validated R9-R13)
__device__ __forceinline__ void mma_bf16(float* c, const uint32_t* a, const uint32_t* b) {
    asm volatile(
        "mma.sync.aligned.m16n8k16.row.col.f32.bf16.bf16.f32 "
        "{%0,%1,%2,%3}, {%4,%5,%6,%7}, {%8,%9}, {%0,%1,%2,%3};"
        : "+f"(c[0]), "+f"(c[1]), "+f"(c[2]), "+f"(c[3])
        : "r"(a[0]), "r"(a[1]), "r"(a[2]), "r"(a[3]), "r"(b[0]), "r"(b[1]));
}

// ============================================================================
// bf16 tensor-core GEMM: out = W @ in (+res+relu if float out)
// CTA 128x128, 256 threads (8 warps 2x4), warp tile 64x32.
// A smem [m][k] pitch 36 words (normal ldsm); B smem [k][n] NATURAL layout,
// pitch 68 words (272B -> trans-ldsm conflict-free), staged with contiguous
// 128-bit global loads. Paths resolved at COMPILE TIME (template) so each
// instantiation carries only its own staging registers.
// ============================================================================
#define PAB 36
#define PBW 68
#define ATILE_W (128 * PAB)                  // 4608 words
#define BTILE_W (32 * PBW)                   // 2176 words
#define STG_W (ATILE_W + BTILE_W)            // 6784 words
#define GEMM_SMEM (2 * STG_W * 4)            // 54272 B

template <int IN_BF16, int OUT_BF16, int DO_RELU>
__global__ void __launch_bounds__(256, 2)
gemm_tc_kernel(const float* __restrict__ Wmat,
               const void* __restrict__ inp,
               const float* __restrict__ res,
               void* __restrict__ outp)
{
    extern __shared__ uint32_t smu[];
    const uint32_t smb = smem_u32(smu);
    uint32_t* Abuf[2] = { smu,           smu + STG_W };
    uint32_t* Bbuf[2] = { smu + ATILE_W, smu + STG_W + ATILE_W };
    const uint32_t abase[2] = { smb,                 smb + STG_W * 4 };
    const uint32_t bbase[2] = { smb + ATILE_W * 4,   smb + (STG_W + ATILE_W) * 4 };

    const int tid  = threadIdx.x;
    const int wid  = tid >> 5;
    const int lane = tid & 31;
    const int g    = lane >> 2;
    const int t    = lane & 3;
    const int wm   = (wid >> 2) * 64;        // 0 or 64
    const int wn   = (wid & 3) * 32;

    const int m0 = blockIdx.x * 128;
    const int n0 = blockIdx.y * 128;
    const int b  = blockIdx.z;
    const float*    inf = (const float*)inp + (size_t)b * ELEMS_PER_IMG;
    const uint32_t* inw = (const uint32_t*)inp + (size_t)b * (ELEMS_PER_IMG / 2);

    // fragment lane offsets (bytes within a stage)
    const uint32_t aoff = ((wm + (lane & 15)) * PAB + ((lane >> 4) << 2)) * 4;
    const uint32_t boff = ((((lane & 7) + ((lane >> 3) & 1) * 8) * PBW)
                           + ((lane >> 4) << 2)) * 4;

    // A staging: thread owns (rr, q0),(rr, q1); quad q covers k=q*8..q*8+7
    const int rr = tid & 127;
    const int q0 = tid >> 7;
    const int q1 = q0 + 2;

    float acc[4][4][4];
#pragma unroll
    for (int f = 0; f < 4; f++)
#pragma unroll
        for (int j = 0; j < 4; j++)
#pragma unroll
            for (int e = 0; e < 4; e++) acc[f][j][e] = 0.0f;

    uint32_t pa[2][4];
    uint32_t pbf[4][2];     // fp32-input path only
    uint4    pbq[2];        // bf16-input path only

    auto load_chunk = [&](int kk) {
#pragma unroll
        for (int it = 0; it < 2; ++it) {
            const int q  = it ? q1 : q0;
            const int kb = kk + q * 8;
            const float* arow = &Wmat[(m0 + rr) * CC + kb];
            float4 a0 = *reinterpret_cast<const float4*>(arow);
            float4 a1 = *reinterpret_cast<const float4*>(arow + 4);
            pa[it][0] = pack_bf16(a0.x, a0.y);
            pa[it][1] = pack_bf16(a0.z, a0.w);
            pa[it][2] = pack_bf16(a1.x, a1.y);
            pa[it][3] = pack_bf16(a1.z, a1.w);
        }
        if (IN_BF16) {
#pragma unroll
            for (int it = 0; it < 2; ++it) {
                const int f = tid + it * 256;
                const int k = f >> 4, n8 = f & 15;
                pbq[it] = *reinterpret_cast<const uint4*>(
                    &inw[(size_t)(kk + k) * (HWSZ / 2) + (n0 >> 1) + n8 * 4]);
            }
        } else {
#pragma unroll
            for (int it = 0; it < 4; ++it) {
                const int f = tid + it * 256;
                const int k = f >> 5, n4 = f & 31;
                float4 v = *reinterpret_cast<const float4*>(
                    &inf[(size_t)(kk + k) * HWSZ + n0 + n4 * 4]);
                pbf[it][0] = pack_bf16(v.x, v.y);
                pbf[it][1] = pack_bf16(v.z, v.w);
            }
        }
    };
    auto store_chunk = [&](int p) {
#pragma unroll
        for (int it = 0; it < 2; ++it) {
            const int q = it ? q1 : q0;
            *reinterpret_cast<uint4*>(&Abuf[p][rr * PAB + q * 4]) =
                *reinterpret_cast<uint4*>(pa[it]);
        }
        if (IN_BF16) {
#pragma unroll
            for (int it = 0; it < 2; ++it) {
                const int f = tid + it * 256;
                const int k = f >> 4, n8 = f & 15;
                *reinterpret_cast<uint4*>(&Bbuf[p][k * PBW + n8 * 4]) = pbq[it];
            }
        } else {
#pragma unroll
            for (int it = 0; it < 4; ++it) {
                const int f = tid + it * 256;
                const int k = f >> 5, n4 = f & 31;
                *reinterpret_cast<uint2*>(&Bbuf[p][k * PBW + n4 * 2]) =
                    *reinterpret_cast<uint2*>(pbf[it]);
            }
        }
    };

    load_chunk(0);
    store_chunk(0);
    __syncthreads();

    for (int i = 0; i < 8; ++i) {
        const int p = i & 1;

        if (i < 7) load_chunk((i + 1) * 32);   // prefetch into regs

        const uint32_t aA = abase[p] + aoff;
        const uint32_t aB = bbase[p] + boff + (wn >> 1) * 4;
#pragma unroll
        for (int ks = 0; ks < 2; ++ks) {
            uint32_t afr[4][4];
#pragma unroll
            for (int f = 0; f < 4; ++f)
                ldsm_x4(afr[f], aA + f * (16 * PAB * 4) + ks * 32);
#pragma unroll
            for (int j2 = 0; j2 < 2; ++j2) {
                uint32_t bfr[4];
                ldsm_x4_t(bfr, aB + j2 * 32 + ks * (16 * PBW * 4));
#pragma unroll
                for (int f = 0; f < 4; ++f) {
                    mma_bf16(acc[f][2 * j2],     afr[f], bfr);
                    mma_bf16(acc[f][2 * j2 + 1], afr[f], bfr + 2);
                }
            }
        }

        if (i < 7) store_chunk(p ^ 1);
        __syncthreads();
    }

    // ---- epilogue ----
    if (OUT_BF16) {
        uint32_t* ob = reinterpret_cast<uint32_t*>(outp) + (size_t)b * (ELEMS_PER_IMG / 2);
#pragma unroll
        for (int f = 0; f < 4; ++f) {
#pragma unroll
            for (int j = 0; j < 4; ++j) {
                const int row = m0 + wm + f * 16 + g;
                const int col = n0 + wn + j * 8 + 2 * t;   // even
                ob[((size_t)row * HWSZ + col) >> 1]       = pack_bf16(acc[f][j][0], acc[f][j][1]);
                ob[((size_t)(row + 8) * HWSZ + col) >> 1] = pack_bf16(acc[f][j][2], acc[f][j][3]);
            }
        }
    } else {
        float* outb = reinterpret_cast<float*>(outp) + (size_t)b * ELEMS_PER_IMG;
        const float* resb = res + (size_t)b * ELEMS_PER_IMG;
#pragma unroll
        for (int f = 0; f < 4; ++f) {
#pragma unroll
            for (int j = 0; j < 4; ++j) {
                const int row = m0 + wm + f * 16 + g;
                const int col = n0 + wn + j * 8 + 2 * t;
                float2 v0 = { acc[f][j][0], acc[f][j][1] };
                float2 v1 = { acc[f][j][2], acc[f][j][3] };
                if (DO_RELU) {
                    float2 r0 = *reinterpret_cast<const float2*>(&resb[(size_t)row * HWSZ + col]);
                    float2 r1 = *reinterpret_cast<const float2*>(&resb[(size_t)(row + 8) * HWSZ + col]);
                    v0.x = fmaxf(v0.x + r0.x, 0.0f);
                    v0.y = fmaxf(v0.y + r0.y, 0.0f);
                    v1.x = fmaxf(v1.x + r1.x, 0.0f);
                    v1.y = fmaxf(v1.y + r1.y, 0.0f);
                }
                *reinterpret_cast<float2*>(&outb[(size_t)row * HWSZ + col]) = v0;
                *reinterpret_cast<float2*>(&outb[(size_t)(row + 8) * HWSZ + col]) = v1;
            }
        }
    }
}

// ============================================================================
// bf16 tensor-core attention per (b,c) — unchanged from R13 (76us, validated).
// ============================================================================
#define PTQ 60
#define ATSZ (HH * PTQ)                 // 6720 words
#define ATTN_SMEM (3 * ATSZ * 4)        // 80640 B

__global__ void __launch_bounds__(224, 2)
attn_tc_kernel(const uint32_t* __restrict__ Qg, const uint32_t* __restrict__ Kg,
               const uint32_t* __restrict__ Vg, uint32_t* __restrict__ Z)
{
    extern __shared__ uint32_t smu[];
    const uint32_t smb = smem_u32(smu);
    uint32_t* Ks = smu;
    uint32_t* Vs = smu + ATSZ;
    uint32_t* Ms = smu + 2 * ATSZ;
    const uint32_t kbase = smb;
    const uint32_t vbase = smb + ATSZ * 4;
    const uint32_t mbase = smb + 2 * ATSZ * 4;

    const size_t wbase = (size_t)blockIdx.x * (HWSZ / 2);
    const int tid  = threadIdx.x;
    const int wid  = tid >> 5;
    const int lane = tid & 31;
    const int g    = lane >> 2;
    const int t    = lane & 3;
    const int r0   = wid * 16;

    const uint32_t* Qb = Qg + wbase;
    const uint32_t* Kb = Kg + wbase;
    const uint32_t* Vb = Vg + wbase;

    for (int i = tid; i < HWSZ / 2; i += 224) {
        const int row = i / 56, jp = i % 56;
        const int o = row * PTQ + jp;
        Ms[o] = Qb[i];
        Ks[o] = Kb[i];
        Vs[o] = Vb[i];
    }
    __syncthreads();

    const uint32_t aoff = ((r0 + (lane & 15)) * PTQ + ((lane >> 4) << 2)) * 4;
    const uint32_t boff = ((((lane & 7) + ((lane >> 3) & 1) * 8) * PTQ)
                           + ((lane >> 4) << 2)) * 4;

    float acc[14][4];
#pragma unroll
    for (int j = 0; j < 14; j++)
#pragma unroll
        for (int e = 0; e < 4; e++) acc[j][e] = 0.0f;

#pragma unroll
    for (int ks = 0; ks < 7; ++ks) {
        uint32_t a[4];
        ldsm_x4(a, mbase + aoff + ks * 32);
#pragma unroll
        for (int j2 = 0; j2 < 7; ++j2) {
            uint32_t bfr[4];
            ldsm_x4_t(bfr, kbase + boff + j2 * 32 + ks * (16 * PTQ * 4));
            mma_bf16(acc[2 * j2],     a, bfr);
            mma_bf16(acc[2 * j2 + 1], a, bfr + 2);
        }
    }

    {
        float mx0 = -1e30f, mx1 = -1e30f;
#pragma unroll
        for (int j = 0; j < 14; ++j) {
            mx0 = fmaxf(mx0, fmaxf(acc[j][0], acc[j][1]));
            mx1 = fmaxf(mx1, fmaxf(acc[j][2], acc[j][3]));
        }
        mx0 = fmaxf(mx0, __shfl_xor_sync(0xffffffffu, mx0, 1));
        mx0 = fmaxf(mx0, __shfl_xor_sync(0xffffffffu, mx0, 2));
        mx1 = fmaxf(mx1, __shfl_xor_sync(0xffffffffu, mx1, 1));
        mx1 = fmaxf(mx1, __shfl_xor_sync(0xffffffffu, mx1, 2));
        float s0 = 0.0f, s1 = 0.0f;
#pragma unroll
        for (int j = 0; j < 14; ++j) {
            acc[j][0] = __expf(acc[j][0] - mx0);
            acc[j][1] = __expf(acc[j][1] - mx0);
            acc[j][2] = __expf(acc[j][2] - mx1);
            acc[j][3] = __expf(acc[j][3] - mx1);
            s0 += acc[j][0] + acc[j][1];
            s1 += acc[j][2] + acc[j][3];
        }
        s0 += __shfl_xor_sync(0xffffffffu, s0, 1);
        s0 += __shfl_xor_sync(0xffffffffu, s0, 2);
        s1 += __shfl_xor_sync(0xffffffffu, s1, 1);
        s1 += __shfl_xor_sync(0xffffffffu, s1, 2);
        const float i0 = 1.0f / s0, i1 = 1.0f / s1;
#pragma unroll
        for (int j = 0; j < 14; ++j) {
            acc[j][0] *= i0; acc[j][1] *= i0;
            acc[j][2] *= i1; acc[j][3] *= i1;
        }
    }

    __syncwarp();
#pragma unroll
    for (int j = 0; j < 14; ++j) {
        Ms[(r0 + g) * PTQ + j * 4 + t]     = pack_bf16(acc[j][0], acc[j][1]);
        Ms[(r0 + g + 8) * PTQ + j * 4 + t] = pack_bf16(acc[j][2], acc[j][3]);
    }
    __syncwarp();

#pragma unroll
    for (int j = 0; j < 14; j++)
#pragma unroll
        for (int e = 0; e < 4; e++) acc[j][e] = 0.0f;

#pragma unroll
    for (int ks = 0; ks < 7; ++ks) {
        uint32_t a[4];
        ldsm_x4(a, mbase + aoff + ks * 32);
#pragma unroll
        for (int j2 = 0; j2 < 7; ++j2) {
            uint32_t bfr[4];
            ldsm_x4_t(bfr, vbase + boff + j2 * 32 + ks * (16 * PTQ * 4));
            mma_bf16(acc[2 * j2],     a, bfr);
            mma_bf16(acc[2 * j2 + 1], a, bfr + 2);
        }
    }

    uint32_t* Zb = Z + wbase;
#pragma unroll
    for (int j = 0; j < 14; ++j) {
        const int col = j * 8 + 2 * t;   // even
        Zb[((r0 + g) * HH + col) >> 1]     = pack_bf16(acc[j][0], acc[j][1]);
        Zb[((r0 + g + 8) * HH + col) >> 1] = pack_bf16(acc[j][2], acc[j][3]);
    }
}

extern "C" void kernel_launch(void* const* d_in, const int* in_sizes, int n_in,
                              void* d_out, int out_size)
{
    const float* x  = (const float*)d_in[0];
    const float* y  = (const float*)d_in[1];
    const float* WQ = (const float*)d_in[2];
    const float* WK = (const float*)d_in[3];
    const float* WV = (const float*)d_in[4];
    const float* WZ = (const float*)d_in[5];
    float* out = (float*)d_out;

    void *dQ, *dK, *dV, *dZ;
    cudaGetSymbolAddress(&dQ, g_Q);
    cudaGetSymbolAddress(&dK, g_K);
    cudaGetSymbolAddress(&dV, g_V);
    cudaGetSymbolAddress(&dZ, g_Zs);

    cudaFuncSetAttribute(attn_tc_kernel, cudaFuncAttributeMaxDynamicSharedMemorySize,
                         ATTN_SMEM);
    cudaFuncSetAttribute(gemm_tc_kernel<0, 1, 0>,
                         cudaFuncAttributeMaxDynamicSharedMemorySize, GEMM_SMEM);
    cudaFuncSetAttribute(gemm_tc_kernel<1, 0, 1>,
                         cudaFuncAttributeMaxDynamicSharedMemorySize, GEMM_SMEM);

    dim3 gg(2, HWSZ / 128, BB);   // m-tile fastest -> B-tile L2 reuse

    gemm_tc_kernel<0, 1, 0><<<gg, 256, GEMM_SMEM>>>(WQ, x, nullptr, dQ);
    gemm_tc_kernel<0, 1, 0><<<gg, 256, GEMM_SMEM>>>(WK, y, nullptr, dK);
    gemm_tc_kernel<0, 1, 0><<<gg, 256, GEMM_SMEM>>>(WV, y, nullptr, dV);
    attn_tc_kernel<<<BB * CC, 224, ATTN_SMEM>>>((const uint32_t*)dQ,
                                                (const uint32_t*)dK,
                                                (const uint32_t*)dV,
                                                (uint32_t*)dZ);
    gemm_tc_kernel<1, 0, 1><<<gg, 256, GEMM_SMEM>>>(WZ, dZ, x, out);
}

// round 15
// speedup vs baseline: 1.7688x; 1.3626x over previous
#include <cuda_runtime.h>
#include <cuda_bf16.h>
#include <cstdint>

// Problem constants
#define BB 8
#define CC 256
#define HH 112
#define HWSZ 12544              // 112*112
#define ELEMS_PER_IMG (CC * HWSZ)
#define TOTAL_ELEMS (BB * ELEMS_PER_IMG)

// Scratch (device globals; no allocations allowed)
__device__ __nv_bfloat16 g_Q[TOTAL_ELEMS];
__device__ __nv_bfloat16 g_K[TOTAL_ELEMS];
__device__ __nv_bfloat16 g_V[TOTAL_ELEMS];
__device__ __nv_bfloat16 g_Zs[TOTAL_ELEMS];
__device__ __nv_bfloat16 g_xb[TOTAL_ELEMS];     // bf16 copy of x
__device__ __nv_bfloat16 g_yb[TOTAL_ELEMS];     // bf16 copy of y
__device__ __nv_bfloat16 g_Wb[4 * CC * CC];     // bf16 copies of WQ,WK,WV,WZ

__device__ __forceinline__ uint32_t smem_u32(const void* p) {
    uint32_t a;
    asm("{ .reg .u64 t; cvta.to.shared.u64 t, %1; cvt.u32.u64 %0, t; }"
        : "=r"(a) : "l"(p));
    return a;
}
// pack two floats into bf16x2: lo -> low half, hi -> high half
__device__ __forceinline__ uint32_t pack_bf16(float lo, float hi) {
    uint32_t r;
    asm("cvt.rn.bf16x2.f32 %0, %1, %2;" : "=r"(r) : "f"(hi), "f"(lo));
    return r;
}
// ldmatrix x4 (normal)
__device__ __forceinline__ void ldsm_x4(uint32_t* r, uint32_t addr) {
    asm volatile("ldmatrix.sync.aligned.m8n8.x4.shared.b16 {%0,%1,%2,%3}, [%4];"
        : "=r"(r[0]), "=r"(r[1]), "=r"(r[2]), "=r"(r[3]) : "r"(addr));
}
// ldmatrix x4 transposed
__device__ __forceinline__ void ldsm_x4_t(uint32_t* r, uint32_t addr) {
    asm volatile("ldmatrix.sync.aligned.m8n8.x4.trans.shared.b16 {%0,%1,%2,%3}, [%4];"
        : "=r"(r[0]), "=r"(r[1]), "=r"(r[2]), "=r"(r[3]) : "r"(addr));
}
// mma.sync m16n8k16 bf16 (fragment layout validated R9-R14)
__device__ __forceinline__ void mma_bf16(float* c, const uint32_t* a, const uint32_t* b) {
    asm volatile(
        "mma.sync.aligned.m16n8k16.row.col.f32.bf16.bf16.f32 "
        "{%0,%1,%2,%3}, {%4,%5,%6,%7}, {%8,%9}, {%0,%1,%2,%3};"
        : "+f"(c[0]), "+f"(c[1]), "+f"(c[2]), "+f"(c[3])
        : "r"(a[0]), "r"(a[1]), "r"(a[2]), "r"(a[3]), "r"(b[0]), "r"(b[1]));
}
// cp.async (baseline PTX sm_80+)
#define CP_ASYNC16(dst, src) \
    asm volatile("cp.async.cg.shared.global [%0], [%1], 16;" \
                 :: "r"(dst), "l"(src) : "memory")
#define CP_COMMIT() asm volatile("cp.async.commit_group;" ::: "memory")
#define CP_WAIT2()  asm volatile("cp.async.wait_group 2;" ::: "memory")

// ============================================================================
// fp32 -> bf16 streaming conversion (grid-stride, float4 -> bf16x2 pairs)
// ============================================================================
__global__ void cvt_bf16_kernel(const float4* __restrict__ src,
                                uint2* __restrict__ dst, int n4)
{
    int i = blockIdx.x * blockDim.x + threadIdx.x;
    const int stride = gridDim.x * blockDim.x;
    for (; i < n4; i += stride) {
        float4 v = src[i];
        dst[i] = make_uint2(pack_bf16(v.x, v.y), pack_bf16(v.z, v.w));
    }
}

// ============================================================================
// bf16 tensor-core GEMM with cp.async 4-stage pipeline.
// CTA 128x128, 256 threads (8 warps 2x4), warp tile 64x32, K=256 in 8 chunks.
// All inputs bf16 (pre-converted). A smem [m][k] pitch 20 words (80B,
// conflict-free normal-ldsm); B smem [k][n] pitch 68 words (trans-ldsm,
// validated). Staging = pure cp.async.cg, 4 per thread per chunk.
// ============================================================================
#define PA 20
#define PBW 68
#define A_STG (128 * PA)                     // 2560 words
#define B_STG (32 * PBW)                     // 2176 words
#define STG (A_STG + B_STG)                  // 4736 words = 18944 B
#define NSTAGE 4
#define CA_SMEM (NSTAGE * STG * 4)           // 75776 B

template <int OUT_BF16, int DO_RELU>
__global__ void __launch_bounds__(256, 2)
gemm_ca_kernel(const __nv_bfloat16* __restrict__ Wb,
               const __nv_bfloat16* __restrict__ inb0,
               const float* __restrict__ res,
               void* __restrict__ outp)
{
    extern __shared__ uint32_t smu[];
    const uint32_t smb = smem_u32(smu);

    const int tid  = threadIdx.x;
    const int wid  = tid >> 5;
    const int lane = tid & 31;
    const int g    = lane >> 2;
    const int t    = lane & 3;
    const int wm   = (wid >> 2) * 64;        // 0 or 64
    const int wn   = (wid & 3) * 32;

    const int m0 = blockIdx.x * 128;
    const int n0 = blockIdx.y * 128;
    const int b  = blockIdx.z;
    const __nv_bfloat16* inb = inb0 + (size_t)b * ELEMS_PER_IMG;

    // fragment lane offsets (bytes within a stage)
    const uint32_t aoff = ((wm + (lane & 15)) * PA + ((lane >> 4) << 2)) * 4;
    const uint32_t boff = ((((lane & 7) + ((lane >> 3) & 1) * 8) * PBW)
                           + ((lane >> 4) << 2)) * 4;

    float acc[4][4][4];
#pragma unroll
    for (int f = 0; f < 4; f++)
#pragma unroll
        for (int j = 0; j < 4; j++)
#pragma unroll
            for (int e = 0; e < 4; e++) acc[f][j][e] = 0.0f;

    // cp.async staging: per thread 2 A-chunks + 2 B-chunks of 16B
    auto issue_chunk = [&](int kk, int s) {
        const uint32_t base = smb + (uint32_t)s * (STG * 4);
#pragma unroll
        for (int it = 0; it < 2; ++it) {
            const int f = tid + it * 256;
            const int ar = f >> 2, ac = f & 3;           // A: 128 rows x 4 16B
            const __nv_bfloat16* asrc = Wb + (size_t)(m0 + ar) * CC + kk + ac * 8;
            CP_ASYNC16(base + (uint32_t)(ar * PA + ac * 4) * 4, asrc);
            const int bk = f >> 4, bn = f & 15;          // B: 32 rows x 16 16B
            const __nv_bfloat16* bsrc = inb + (size_t)(kk + bk) * HWSZ + n0 + bn * 8;
            CP_ASYNC16(base + (uint32_t)(A_STG * 4) + (uint32_t)(bk * PBW + bn * 4) * 4, bsrc);
        }
        CP_COMMIT();
    };

    issue_chunk(0, 0);
    issue_chunk(32, 1);
    issue_chunk(64, 2);

    for (int i = 0; i < 8; ++i) {
        CP_WAIT2();          // chunk i's group complete (empty commits pad)
        __syncthreads();

        if (i < 5) issue_chunk((i + 3) * 32, (i + 3) & 3);
        else       CP_COMMIT();   // empty group keeps wait depth uniform

        const int s = i & 3;
        const uint32_t aA = smb + (uint32_t)s * (STG * 4) + aoff;
        const uint32_t aB = smb + (uint32_t)s * (STG * 4) + A_STG * 4 + boff
                          + (wn >> 1) * 4;
#pragma unroll
        for (int ks = 0; ks < 2; ++ks) {
            uint32_t afr[4][4];
#pragma unroll
            for (int f = 0; f < 4; ++f)
                ldsm_x4(afr[f], aA + f * (16 * PA * 4) + ks * 32);
#pragma unroll
            for (int j2 = 0; j2 < 2; ++j2) {
                uint32_t bfr[4];
                ldsm_x4_t(bfr, aB + j2 * 32 + ks * (16 * PBW * 4));
#pragma unroll
                for (int f = 0; f < 4; ++f) {
                    mma_bf16(acc[f][2 * j2],     afr[f], bfr);
                    mma_bf16(acc[f][2 * j2 + 1], afr[f], bfr + 2);
                }
            }
        }
    }

    // ---- epilogue ----
    if (OUT_BF16) {
        uint32_t* ob = reinterpret_cast<uint32_t*>(outp) + (size_t)b * (ELEMS_PER_IMG / 2);
#pragma unroll
        for (int f = 0; f < 4; ++f) {
#pragma unroll
            for (int j = 0; j < 4; ++j) {
                const int row = m0 + wm + f * 16 + g;
                const int col = n0 + wn + j * 8 + 2 * t;   // even
                ob[((size_t)row * HWSZ + col) >> 1]       = pack_bf16(acc[f][j][0], acc[f][j][1]);
                ob[((size_t)(row + 8) * HWSZ + col) >> 1] = pack_bf16(acc[f][j][2], acc[f][j][3]);
            }
        }
    } else {
        float* outb = reinterpret_cast<float*>(outp) + (size_t)b * ELEMS_PER_IMG;
        const float* resb = res + (size_t)b * ELEMS_PER_IMG;
#pragma unroll
        for (int f = 0; f < 4; ++f) {
#pragma unroll
            for (int j = 0; j < 4; ++j) {
                const int row = m0 + wm + f * 16 + g;
                const int col = n0 + wn + j * 8 + 2 * t;
                float2 v0 = { acc[f][j][0], acc[f][j][1] };
                float2 v1 = { acc[f][j][2], acc[f][j][3] };
                if (DO_RELU) {
                    float2 r0 = *reinterpret_cast<const float2*>(&resb[(size_t)row * HWSZ + col]);
                    float2 r1 = *reinterpret_cast<const float2*>(&resb[(size_t)(row + 8) * HWSZ + col]);
                    v0.x = fmaxf(v0.x + r0.x, 0.0f);
                    v0.y = fmaxf(v0.y + r0.y, 0.0f);
                    v1.x = fmaxf(v1.x + r1.x, 0.0f);
                    v1.y = fmaxf(v1.y + r1.y, 0.0f);
                }
                *reinterpret_cast<float2*>(&outb[(size_t)row * HWSZ + col]) = v0;
                *reinterpret_cast<float2*>(&outb[(size_t)(row + 8) * HWSZ + col]) = v1;
            }
        }
    }
}

// ============================================================================
// bf16 tensor-core attention per (b,c) — unchanged from R13/R14 (76us).
// ============================================================================
#define PTQ 60
#define ATSZ (HH * PTQ)                 // 6720 words
#define ATTN_SMEM (3 * ATSZ * 4)        // 80640 B

__global__ void __launch_bounds__(224, 2)
attn_tc_kernel(const uint32_t* __restrict__ Qg, const uint32_t* __restrict__ Kg,
               const uint32_t* __restrict__ Vg, uint32_t* __restrict__ Z)
{
    extern __shared__ uint32_t smu[];
    const uint32_t smb = smem_u32(smu);
    uint32_t* Ks = smu;
    uint32_t* Vs = smu + ATSZ;
    uint32_t* Ms = smu + 2 * ATSZ;
    const uint32_t kbase = smb;
    const uint32_t vbase = smb + ATSZ * 4;
    const uint32_t mbase = smb + 2 * ATSZ * 4;

    const size_t wbase = (size_t)blockIdx.x * (HWSZ / 2);
    const int tid  = threadIdx.x;
    const int wid  = tid >> 5;
    const int lane = tid & 31;
    const int g    = lane >> 2;
    const int t    = lane & 3;
    const int r0   = wid * 16;

    const uint32_t* Qb = Qg + wbase;
    const uint32_t* Kb = Kg + wbase;
    const uint32_t* Vb = Vg + wbase;

    for (int i = tid; i < HWSZ / 2; i += 224) {
        const int row = i / 56, jp = i % 56;
        const int o = row * PTQ + jp;
        Ms[o] = Qb[i];
        Ks[o] = Kb[i];
        Vs[o] = Vb[i];
    }
    __syncthreads();

    const uint32_t aoff = ((r0 + (lane & 15)) * PTQ + ((lane >> 4) << 2)) * 4;
    const uint32_t boff = ((((lane & 7) + ((lane >> 3) & 1) * 8) * PTQ)
                           + ((lane >> 4) << 2)) * 4;

    float acc[14][4];
#pragma unroll
    for (int j = 0; j < 14; j++)
#pragma unroll
        for (int e = 0; e < 4; e++) acc[j][e] = 0.0f;

#pragma unroll
    for (int ks = 0; ks < 7; ++ks) {
        uint32_t a[4];
        ldsm_x4(a, mbase + aoff + ks * 32);
#pragma unroll
        for (int j2 = 0; j2 < 7; ++j2) {
            uint32_t bfr[4];
            ldsm_x4_t(bfr, kbase + boff + j2 * 32 + ks * (16 * PTQ * 4));
            mma_bf16(acc[2 * j2],     a, bfr);
            mma_bf16(acc[2 * j2 + 1], a, bfr + 2);
        }
    }

    {
        float mx0 = -1e30f, mx1 = -1e30f;
#pragma unroll
        for (int j = 0; j < 14; ++j) {
            mx0 = fmaxf(mx0, fmaxf(acc[j][0], acc[j][1]));
            mx1 = fmaxf(mx1, fmaxf(acc[j][2], acc[j][3]));
        }
        mx0 = fmaxf(mx0, __shfl_xor_sync(0xffffffffu, mx0, 1));
        mx0 = fmaxf(mx0, __shfl_xor_sync(0xffffffffu, mx0, 2));
        mx1 = fmaxf(mx1, __shfl_xor_sync(0xffffffffu, mx1, 1));
        mx1 = fmaxf(mx1, __shfl_xor_sync(0xffffffffu, mx1, 2));
        float s0 = 0.0f, s1 = 0.0f;
#pragma unroll
        for (int j = 0; j < 14; ++j) {
            acc[j][0] = __expf(acc[j][0] - mx0);
            acc[j][1] = __expf(acc[j][1] - mx0);
            acc[j][2] = __expf(acc[j][2] - mx1);
            acc[j][3] = __expf(acc[j][3] - mx1);
            s0 += acc[j][0] + acc[j][1];
            s1 += acc[j][2] + acc[j][3];
        }
        s0 += __shfl_xor_sync(0xffffffffu, s0, 1);
        s0 += __shfl_xor_sync(0xffffffffu, s0, 2);
        s1 += __shfl_xor_sync(0xffffffffu, s1, 1);
        s1 += __shfl_xor_sync(0xffffffffu, s1, 2);
        const float i0 = 1.0f / s0, i1 = 1.0f / s1;
#pragma unroll
        for (int j = 0; j < 14; ++j) {
            acc[j][0] *= i0; acc[j][1] *= i0;
            acc[j][2] *= i1; acc[j][3] *= i1;
        }
    }

    __syncwarp();
#pragma unroll
    for (int j = 0; j < 14; ++j) {
        Ms[(r0 + g) * PTQ + j * 4 + t]     = pack_bf16(acc[j][0], acc[j][1]);
        Ms[(r0 + g + 8) * PTQ + j * 4 + t] = pack_bf16(acc[j][2], acc[j][3]);
    }
    __syncwarp();

#pragma unroll
    for (int j = 0; j < 14; j++)
#pragma unroll
        for (int e = 0; e < 4; e++) acc[j][e] = 0.0f;

#pragma unroll
    for (int ks = 0; ks < 7; ++ks) {
        uint32_t a[4];
        ldsm_x4(a, mbase + aoff + ks * 32);
#pragma unroll
        for (int j2 = 0; j2 < 7; ++j2) {
            uint32_t bfr[4];
            ldsm_x4_t(bfr, vbase + boff + j2 * 32 + ks * (16 * PTQ * 4));
            mma_bf16(acc[2 * j2],     a, bfr);
            mma_bf16(acc[2 * j2 + 1], a, bfr + 2);
        }
    }

    uint32_t* Zb = Z + wbase;
#pragma unroll
    for (int j = 0; j < 14; ++j) {
        const int col = j * 8 + 2 * t;   // even
        Zb[((r0 + g) * HH + col) >> 1]     = pack_bf16(acc[j][0], acc[j][1]);
        Zb[((r0 + g + 8) * HH + col) >> 1] = pack_bf16(acc[j][2], acc[j][3]);
    }
}

extern "C" void kernel_launch(void* const* d_in, const int* in_sizes, int n_in,
                              void* d_out, int out_size)
{
    const float* x  = (const float*)d_in[0];
    const float* y  = (const float*)d_in[1];
    const float* WQ = (const float*)d_in[2];
    const float* WK = (const float*)d_in[3];
    const float* WV = (const float*)d_in[4];
    const float* WZ = (const float*)d_in[5];
    float* out = (float*)d_out;

    void *dQ, *dK, *dV, *dZ, *dxb, *dyb, *dWb;
    cudaGetSymbolAddress(&dQ, g_Q);
    cudaGetSymbolAddress(&dK, g_K);
    cudaGetSymbolAddress(&dV, g_V);
    cudaGetSymbolAddress(&dZ, g_Zs);
    cudaGetSymbolAddress(&dxb, g_xb);
    cudaGetSymbolAddress(&dyb, g_yb);
    cudaGetSymbolAddress(&dWb, g_Wb);

    cudaFuncSetAttribute(attn_tc_kernel, cudaFuncAttributeMaxDynamicSharedMemorySize,
                         ATTN_SMEM);
    cudaFuncSetAttribute(gemm_ca_kernel<1, 0>,
                         cudaFuncAttributeMaxDynamicSharedMemorySize, CA_SMEM);
    cudaFuncSetAttribute(gemm_ca_kernel<0, 1>,
                         cudaFuncAttributeMaxDynamicSharedMemorySize, CA_SMEM);

    __nv_bfloat16* xb = (__nv_bfloat16*)dxb;
    __nv_bfloat16* yb = (__nv_bfloat16*)dyb;
    __nv_bfloat16* Wb = (__nv_bfloat16*)dWb;

    // ---- prep: fp32 -> bf16 conversions (numerics identical to in-GEMM cvt)
    const int n4big = TOTAL_ELEMS / 4;
    const int n4w   = (CC * CC) / 4;
    cvt_bf16_kernel<<<4096, 256>>>((const float4*)x, (uint2*)xb, n4big);
    cvt_bf16_kernel<<<4096, 256>>>((const float4*)y, (uint2*)yb, n4big);
    cvt_bf16_kernel<<<64, 256>>>((const float4*)WQ, (uint2*)(Wb + 0 * CC * CC), n4w);
    cvt_bf16_kernel<<<64, 256>>>((const float4*)WK, (uint2*)(Wb + 1 * CC * CC), n4w);
    cvt_bf16_kernel<<<64, 256>>>((const float4*)WV, (uint2*)(Wb + 2 * CC * CC), n4w);
    cvt_bf16_kernel<<<64, 256>>>((const float4*)WZ, (uint2*)(Wb + 3 * CC * CC), n4w);

    dim3 gg(2, HWSZ / 128, BB);   // m-tile fastest -> B-tile L2 reuse

    gemm_ca_kernel<1, 0><<<gg, 256, CA_SMEM>>>(Wb + 0 * CC * CC, xb, nullptr, dQ);
    gemm_ca_kernel<1, 0><<<gg, 256, CA_SMEM>>>(Wb + 1 * CC * CC, yb, nullptr, dK);
    gemm_ca_kernel<1, 0><<<gg, 256, CA_SMEM>>>(Wb + 2 * CC * CC, yb, nullptr, dV);
    attn_tc_kernel<<<BB * CC, 224, ATTN_SMEM>>>((const uint32_t*)dQ,
                                                (const uint32_t*)dK,
                                                (const uint32_t*)dV,
                                                (uint32_t*)dZ);
    gemm_ca_kernel<0, 1><<<gg, 256, CA_SMEM>>>(Wb + 3 * CC * CC,
                                               (const __nv_bfloat16*)dZ, x, out);
}

// round 16
// speedup vs baseline: 1.9298x; 1.0910x over previous
#include <cuda_runtime.h>
#include <cuda_bf16.h>
#include <cstdint>

// Problem constants
#define BB 8
#define CC 256
#define HH 112
#define HWSZ 12544              // 112*112
#define ELEMS_PER_IMG (CC * HWSZ)
#define TOTAL_ELEMS (BB * ELEMS_PER_IMG)

// Scratch (device globals; no allocations allowed)
__device__ __nv_bfloat16 g_Q[TOTAL_ELEMS];
__device__ __nv_bfloat16 g_K[TOTAL_ELEMS];
__device__ __nv_bfloat16 g_V[TOTAL_ELEMS];
__device__ __nv_bfloat16 g_Zs[TOTAL_ELEMS];
__device__ __nv_bfloat16 g_xb[TOTAL_ELEMS];     // bf16 copy of x
__device__ __nv_bfloat16 g_yb[TOTAL_ELEMS];     // bf16 copy of y
__device__ __nv_bfloat16 g_Wb[4 * CC * CC];     // bf16 copies of WQ,WK,WV,WZ

__device__ __forceinline__ uint32_t smem_u32(const void* p) {
    uint32_t a;
    asm("{ .reg .u64 t; cvta.to.shared.u64 t, %1; cvt.u32.u64 %0, t; }"
        : "=r"(a) : "l"(p));
    return a;
}
// pack two floats into bf16x2: lo -> low half, hi -> high half
__device__ __forceinline__ uint32_t pack_bf16(float lo, float hi) {
    uint32_t r;
    asm("cvt.rn.bf16x2.f32 %0, %1, %2;" : "=r"(r) : "f"(hi), "f"(lo));
    return r;
}
// ldmatrix x4 (normal)
__device__ __forceinline__ void ldsm_x4(uint32_t* r, uint32_t addr) {
    asm volatile("ldmatrix.sync.aligned.m8n8.x4.shared.b16 {%0,%1,%2,%3}, [%4];"
        : "=r"(r[0]), "=r"(r[1]), "=r"(r[2]), "=r"(r[3]) : "r"(addr));
}
// ldmatrix x4 transposed
__device__ __forceinline__ void ldsm_x4_t(uint32_t* r, uint32_t addr) {
    asm volatile("ldmatrix.sync.aligned.m8n8.x4.trans.shared.b16 {%0,%1,%2,%3}, [%4];"
        : "=r"(r[0]), "=r"(r[1]), "=r"(r[2]), "=r"(r[3]) : "r"(addr));
}
// mma.sync m16n8k16 bf16 (fragment layout validated R9-R15)
__device__ __forceinline__ void mma_bf16(float* c, const uint32_t* a, const uint32_t* b) {
    asm volatile(
        "mma.sync.aligned.m16n8k16.row.col.f32.bf16.bf16.f32 "
        "{%0,%1,%2,%3}, {%4,%5,%6,%7}, {%8,%9}, {%0,%1,%2,%3};"
        : "+f"(c[0]), "+f"(c[1]), "+f"(c[2]), "+f"(c[3])
        : "r"(a[0]), "r"(a[1]), "r"(a[2]), "r"(a[3]), "r"(b[0]), "r"(b[1]));
}
// cp.async (baseline PTX sm_80+)
#define CP_ASYNC16(dst, src) \
    asm volatile("cp.async.cg.shared.global [%0], [%1], 16;" \
                 :: "r"(dst), "l"(src) : "memory")
#define CP_COMMIT() asm volatile("cp.async.commit_group;" ::: "memory")
#define CP_WAIT2()  asm volatile("cp.async.wait_group 2;" ::: "memory")
#define CP_WAIT0()  asm volatile("cp.async.wait_group 0;" ::: "memory")

// ============================================================================
// Fused fp32 -> bf16 conversion for x, y, WQ, WK, WV, WZ in ONE launch.
// Index space: [0, n4big) -> x ; [n4big, 2*n4big) -> y ; then 4 W blocks.
// ============================================================================
#define N4BIG (TOTAL_ELEMS / 4)
#define N4W   ((CC * CC) / 4)
#define N4TOT (2 * N4BIG + 4 * N4W)

__global__ void cvt_all_kernel(const float4* __restrict__ x,
                               const float4* __restrict__ y,
                               const float4* __restrict__ wq,
                               const float4* __restrict__ wk,
                               const float4* __restrict__ wv,
                               const float4* __restrict__ wz,
                               uint2* __restrict__ xb,
                               uint2* __restrict__ yb,
                               uint2* __restrict__ wb)
{
    int i = blockIdx.x * blockDim.x + threadIdx.x;
    const int stride = gridDim.x * blockDim.x;
    for (; i < N4TOT; i += stride) {
        const float4* src;
        uint2* dst;
        int idx;
        if (i < N4BIG)            { src = x;  dst = xb; idx = i; }
        else if (i < 2 * N4BIG)   { src = y;  dst = yb; idx = i - N4BIG; }
        else {
            const int j = i - 2 * N4BIG;
            const int w = j / N4W;
            idx = j - w * N4W;
            src = (w == 0) ? wq : (w == 1) ? wk : (w == 2) ? wv : wz;
            dst = wb + (size_t)w * N4W;
        }
        float4 v = src[idx];
        dst[idx] = make_uint2(pack_bf16(v.x, v.y), pack_bf16(v.z, v.w));
    }
}

// ============================================================================
// bf16 tensor-core GEMM with cp.async 4-stage pipeline (unchanged from R15).
// ============================================================================
#define PA 20
#define PBW 68
#define A_STG (128 * PA)                     // 2560 words
#define B_STG (32 * PBW)                     // 2176 words
#define STG (A_STG + B_STG)                  // 4736 words = 18944 B
#define NSTAGE 4
#define CA_SMEM (NSTAGE * STG * 4)           // 75776 B

template <int OUT_BF16, int DO_RELU>
__global__ void __launch_bounds__(256, 2)
gemm_ca_kernel(const __nv_bfloat16* __restrict__ Wb,
               const __nv_bfloat16* __restrict__ inb0,
               const float* __restrict__ res,
               void* __restrict__ outp)
{
    extern __shared__ uint32_t smu[];
    const uint32_t smb = smem_u32(smu);

    const int tid  = threadIdx.x;
    const int wid  = tid >> 5;
    const int lane = tid & 31;
    const int g    = lane >> 2;
    const int t    = lane & 3;
    const int wm   = (wid >> 2) * 64;        // 0 or 64
    const int wn   = (wid & 3) * 32;

    const int m0 = blockIdx.x * 128;
    const int n0 = blockIdx.y * 128;
    const int b  = blockIdx.z;
    const __nv_bfloat16* inb = inb0 + (size_t)b * ELEMS_PER_IMG;

    const uint32_t aoff = ((wm + (lane & 15)) * PA + ((lane >> 4) << 2)) * 4;
    const uint32_t boff = ((((lane & 7) + ((lane >> 3) & 1) * 8) * PBW)
                           + ((lane >> 4) << 2)) * 4;

    float acc[4][4][4];
#pragma unroll
    for (int f = 0; f < 4; f++)
#pragma unroll
        for (int j = 0; j < 4; j++)
#pragma unroll
            for (int e = 0; e < 4; e++) acc[f][j][e] = 0.0f;

    auto issue_chunk = [&](int kk, int s) {
        const uint32_t base = smb + (uint32_t)s * (STG * 4);
#pragma unroll
        for (int it = 0; it < 2; ++it) {
            const int f = tid + it * 256;
            const int ar = f >> 2, ac = f & 3;           // A: 128 rows x 4 16B
            const __nv_bfloat16* asrc = Wb + (size_t)(m0 + ar) * CC + kk + ac * 8;
            CP_ASYNC16(base + (uint32_t)(ar * PA + ac * 4) * 4, asrc);
            const int bk = f >> 4, bn = f & 15;          // B: 32 rows x 16 16B
            const __nv_bfloat16* bsrc = inb + (size_t)(kk + bk) * HWSZ + n0 + bn * 8;
            CP_ASYNC16(base + (uint32_t)(A_STG * 4) + (uint32_t)(bk * PBW + bn * 4) * 4, bsrc);
        }
        CP_COMMIT();
    };

    issue_chunk(0, 0);
    issue_chunk(32, 1);
    issue_chunk(64, 2);

    for (int i = 0; i < 8; ++i) {
        CP_WAIT2();
        __syncthreads();

        if (i < 5) issue_chunk((i + 3) * 32, (i + 3) & 3);
        else       CP_COMMIT();   // empty group keeps wait depth uniform

        const int s = i & 3;
        const uint32_t aA = smb + (uint32_t)s * (STG * 4) + aoff;
        const uint32_t aB = smb + (uint32_t)s * (STG * 4) + A_STG * 4 + boff
                          + (wn >> 1) * 4;
#pragma unroll
        for (int ks = 0; ks < 2; ++ks) {
            uint32_t afr[4][4];
#pragma unroll
            for (int f = 0; f < 4; ++f)
                ldsm_x4(afr[f], aA + f * (16 * PA * 4) + ks * 32);
#pragma unroll
            for (int j2 = 0; j2 < 2; ++j2) {
                uint32_t bfr[4];
                ldsm_x4_t(bfr, aB + j2 * 32 + ks * (16 * PBW * 4));
#pragma unroll
                for (int f = 0; f < 4; ++f) {
                    mma_bf16(acc[f][2 * j2],     afr[f], bfr);
                    mma_bf16(acc[f][2 * j2 + 1], afr[f], bfr + 2);
                }
            }
        }
    }

    if (OUT_BF16) {
        uint32_t* ob = reinterpret_cast<uint32_t*>(outp) + (size_t)b * (ELEMS_PER_IMG / 2);
#pragma unroll
        for (int f = 0; f < 4; ++f) {
#pragma unroll
            for (int j = 0; j < 4; ++j) {
                const int row = m0 + wm + f * 16 + g;
                const int col = n0 + wn + j * 8 + 2 * t;   // even
                ob[((size_t)row * HWSZ + col) >> 1]       = pack_bf16(acc[f][j][0], acc[f][j][1]);
                ob[((size_t)(row + 8) * HWSZ + col) >> 1] = pack_bf16(acc[f][j][2], acc[f][j][3]);
            }
        }
    } else {
        float* outb = reinterpret_cast<float*>(outp) + (size_t)b * ELEMS_PER_IMG;
        const float* resb = res + (size_t)b * ELEMS_PER_IMG;
#pragma unroll
        for (int f = 0; f < 4; ++f) {
#pragma unroll
            for (int j = 0; j < 4; ++j) {
                const int row = m0 + wm + f * 16 + g;
                const int col = n0 + wn + j * 8 + 2 * t;
                float2 v0 = { acc[f][j][0], acc[f][j][1] };
                float2 v1 = { acc[f][j][2], acc[f][j][3] };
                if (DO_RELU) {
                    float2 r0 = *reinterpret_cast<const float2*>(&resb[(size_t)row * HWSZ + col]);
                    float2 r1 = *reinterpret_cast<const float2*>(&resb[(size_t)(row + 8) * HWSZ + col]);
                    v0.x = fmaxf(v0.x + r0.x, 0.0f);
                    v0.y = fmaxf(v0.y + r0.y, 0.0f);
                    v1.x = fmaxf(v1.x + r1.x, 0.0f);
                    v1.y = fmaxf(v1.y + r1.y, 0.0f);
                }
                *reinterpret_cast<float2*>(&outb[(size_t)row * HWSZ + col]) = v0;
                *reinterpret_cast<float2*>(&outb[(size_t)(row + 8) * HWSZ + col]) = v1;
            }
        }
    }
}

// ============================================================================
// bf16 tensor-core attention per (b,c): cp.async staging (NEW), compute core
// unchanged from R13-R15 (validated).
// ============================================================================
#define PTQ 60
#define ATSZ (HH * PTQ)                 // 6720 words
#define ATTN_SMEM (3 * ATSZ * 4)        // 80640 B

__global__ void __launch_bounds__(224, 2)
attn_tc_kernel(const __nv_bfloat16* __restrict__ Qg,
               const __nv_bfloat16* __restrict__ Kg,
               const __nv_bfloat16* __restrict__ Vg,
               uint32_t* __restrict__ Z)
{
    extern __shared__ uint32_t smu[];
    const uint32_t smb = smem_u32(smu);
    uint32_t* Ms = smu + 2 * ATSZ;
    const uint32_t kbase = smb;
    const uint32_t vbase = smb + ATSZ * 4;
    const uint32_t mbase = smb + 2 * ATSZ * 4;

    const size_t ebase = (size_t)blockIdx.x * HWSZ;    // element base
    const int tid  = threadIdx.x;
    const int wid  = tid >> 5;
    const int lane = tid & 31;
    const int g    = lane >> 2;
    const int t    = lane & 3;
    const int r0   = wid * 16;

    // ---- cp.async staging: 112 rows x 14 16B-chunks per tensor ----
    // global row stride 224B, smem row stride 240B; all 16B-aligned.
    {
        const __nv_bfloat16* Qb = Qg + ebase;
        const __nv_bfloat16* Kb = Kg + ebase;
        const __nv_bfloat16* Vb = Vg + ebase;
        for (int i = tid; i < HH * 14; i += 224) {
            const int row = i / 14, c = i % 14;
            const uint32_t so = (uint32_t)(row * PTQ + c * 4) * 4;
            const size_t   go = (size_t)row * HH + c * 8;
            CP_ASYNC16(mbase + so, Qb + go);
            CP_ASYNC16(kbase + so, Kb + go);
            CP_ASYNC16(vbase + so, Vb + go);
        }
        CP_COMMIT();
        CP_WAIT0();
    }
    __syncthreads();

    const uint32_t aoff = ((r0 + (lane & 15)) * PTQ + ((lane >> 4) << 2)) * 4;
    const uint32_t boff = ((((lane & 7) + ((lane >> 3) & 1) * 8) * PTQ)
                           + ((lane >> 4) << 2)) * 4;

    float acc[14][4];
#pragma unroll
    for (int j = 0; j < 14; j++)
#pragma unroll
        for (int e = 0; e < 4; e++) acc[j][e] = 0.0f;

    // ---- S = Q @ K ----
#pragma unroll
    for (int ks = 0; ks < 7; ++ks) {
        uint32_t a[4];
        ldsm_x4(a, mbase + aoff + ks * 32);
#pragma unroll
        for (int j2 = 0; j2 < 7; ++j2) {
            uint32_t bfr[4];
            ldsm_x4_t(bfr, kbase + boff + j2 * 32 + ks * (16 * PTQ * 4));
            mma_bf16(acc[2 * j2],     a, bfr);
            mma_bf16(acc[2 * j2 + 1], a, bfr + 2);
        }
    }

    // ---- softmax ----
    {
        float mx0 = -1e30f, mx1 = -1e30f;
#pragma unroll
        for (int j = 0; j < 14; ++j) {
            mx0 = fmaxf(mx0, fmaxf(acc[j][0], acc[j][1]));
            mx1 = fmaxf(mx1, fmaxf(acc[j][2], acc[j][3]));
        }
        mx0 = fmaxf(mx0, __shfl_xor_sync(0xffffffffu, mx0, 1));
        mx0 = fmaxf(mx0, __shfl_xor_sync(0xffffffffu, mx0, 2));
        mx1 = fmaxf(mx1, __shfl_xor_sync(0xffffffffu, mx1, 1));
        mx1 = fmaxf(mx1, __shfl_xor_sync(0xffffffffu, mx1, 2));
        float s0 = 0.0f, s1 = 0.0f;
#pragma unroll
        for (int j = 0; j < 14; ++j) {
            acc[j][0] = __expf(acc[j][0] - mx0);
            acc[j][1] = __expf(acc[j][1] - mx0);
            acc[j][2] = __expf(acc[j][2] - mx1);
            acc[j][3] = __expf(acc[j][3] - mx1);
            s0 += acc[j][0] + acc[j][1];
            s1 += acc[j][2] + acc[j][3];
        }
        s0 += __shfl_xor_sync(0xffffffffu, s0, 1);
        s0 += __shfl_xor_sync(0xffffffffu, s0, 2);
        s1 += __shfl_xor_sync(0xffffffffu, s1, 1);
        s1 += __shfl_xor_sync(0xffffffffu, s1, 2);
        const float i0 = 1.0f / s0, i1 = 1.0f / s1;
#pragma unroll
        for (int j = 0; j < 14; ++j) {
            acc[j][0] *= i0; acc[j][1] *= i0;
            acc[j][2] *= i1; acc[j][3] *= i1;
        }
    }

    // ---- write M (bf16) into Ms; rows warp-private ----
    __syncwarp();
#pragma unroll
    for (int j = 0; j < 14; ++j) {
        Ms[(r0 + g) * PTQ + j * 4 + t]     = pack_bf16(acc[j][0], acc[j][1]);
        Ms[(r0 + g + 8) * PTQ + j * 4 + t] = pack_bf16(acc[j][2], acc[j][3]);
    }
    __syncwarp();

    // ---- Z = M @ V ----
#pragma unroll
    for (int j = 0; j < 14; j++)
#pragma unroll
        for (int e = 0; e < 4; e++) acc[j][e] = 0.0f;

#pragma unroll
    for (int ks = 0; ks < 7; ++ks) {
        uint32_t a[4];
        ldsm_x4(a, mbase + aoff + ks * 32);
#pragma unroll
        for (int j2 = 0; j2 < 7; ++j2) {
            uint32_t bfr[4];
            ldsm_x4_t(bfr, vbase + boff + j2 * 32 + ks * (16 * PTQ * 4));
            mma_bf16(acc[2 * j2],     a, bfr);
            mma_bf16(acc[2 * j2 + 1], a, bfr + 2);
        }
    }

    // ---- store Z as packed bf16 words ----
    uint32_t* Zb = Z + ebase / 2;
#pragma unroll
    for (int j = 0; j < 14; ++j) {
        const int col = j * 8 + 2 * t;   // even
        Zb[((r0 + g) * HH + col) >> 1]     = pack_bf16(acc[j][0], acc[j][1]);
        Zb[((r0 + g + 8) * HH + col) >> 1] = pack_bf16(acc[j][2], acc[j][3]);
    }
}

extern "C" void kernel_launch(void* const* d_in, const int* in_sizes, int n_in,
                              void* d_out, int out_size)
{
    const float* x  = (const float*)d_in[0];
    const float* y  = (const float*)d_in[1];
    const float* WQ = (const float*)d_in[2];
    const float* WK = (const float*)d_in[3];
    const float* WV = (const float*)d_in[4];
    const float* WZ = (const float*)d_in[5];
    float* out = (float*)d_out;

    void *dQ, *dK, *dV, *dZ, *dxb, *dyb, *dWb;
    cudaGetSymbolAddress(&dQ, g_Q);
    cudaGetSymbolAddress(&dK, g_K);
    cudaGetSymbolAddress(&dV, g_V);
    cudaGetSymbolAddress(&dZ, g_Zs);
    cudaGetSymbolAddress(&dxb, g_xb);
    cudaGetSymbolAddress(&dyb, g_yb);
    cudaGetSymbolAddress(&dWb, g_Wb);

    cudaFuncSetAttribute(attn_tc_kernel, cudaFuncAttributeMaxDynamicSharedMemorySize,
                         ATTN_SMEM);
    cudaFuncSetAttribute(gemm_ca_kernel<1, 0>,
                         cudaFuncAttributeMaxDynamicSharedMemorySize, CA_SMEM);
    cudaFuncSetAttribute(gemm_ca_kernel<0, 1>,
                         cudaFuncAttributeMaxDynamicSharedMemorySize, CA_SMEM);

    __nv_bfloat16* xb = (__nv_bfloat16*)dxb;
    __nv_bfloat16* yb = (__nv_bfloat16*)dyb;
    __nv_bfloat16* Wb = (__nv_bfloat16*)dWb;

    // ---- prep: ONE fused fp32 -> bf16 conversion launch ----
    cvt_all_kernel<<<2368, 256>>>((const float4*)x, (const float4*)y,
                                  (const float4*)WQ, (const float4*)WK,
                                  (const float4*)WV, (const float4*)WZ,
                                  (uint2*)xb, (uint2*)yb, (uint2*)Wb);

    dim3 gg(2, HWSZ / 128, BB);   // m-tile fastest -> B-tile L2 reuse

    gemm_ca_kernel<1, 0><<<gg, 256, CA_SMEM>>>(Wb + 0 * CC * CC, xb, nullptr, dQ);
    gemm_ca_kernel<1, 0><<<gg, 256, CA_SMEM>>>(Wb + 1 * CC * CC, yb, nullptr, dK);
    gemm_ca_kernel<1, 0><<<gg, 256, CA_SMEM>>>(Wb + 2 * CC * CC, yb, nullptr, dV);
    attn_tc_kernel<<<BB * CC, 224, ATTN_SMEM>>>((const __nv_bfloat16*)dQ,
                                                (const __nv_bfloat16*)dK,
                                                (const __nv_bfloat16*)dV,
                                                (uint32_t*)dZ);
    gemm_ca_kernel<0, 1><<<gg, 256, CA_SMEM>>>(Wb + 3 * CC * CC,
                                               (const __nv_bfloat16*)dZ, x, out);
}

// round 17
// speedup vs baseline: 2.0301x; 1.0520x over previous
#include <cuda_runtime.h>
#include <cuda_bf16.h>
#include <cstdint>

// Problem constants
#define BB 8
#define CC 256
#define HH 112
#define HWSZ 12544              // 112*112
#define ELEMS_PER_IMG (CC * HWSZ)
#define TOTAL_ELEMS (BB * ELEMS_PER_IMG)

// Scratch (device globals; no allocations allowed)
__device__ __nv_bfloat16 g_Q[TOTAL_ELEMS];
__device__ __nv_bfloat16 g_K[TOTAL_ELEMS];
__device__ __nv_bfloat16 g_V[TOTAL_ELEMS];
__device__ __nv_bfloat16 g_Zs[TOTAL_ELEMS];
__device__ __nv_bfloat16 g_xb[TOTAL_ELEMS];     // bf16 copy of x
__device__ __nv_bfloat16 g_yb[TOTAL_ELEMS];     // bf16 copy of y
__device__ __nv_bfloat16 g_Wb[4 * CC * CC];     // bf16 copies of WQ,WK,WV,WZ

__device__ __forceinline__ uint32_t smem_u32(const void* p) {
    uint32_t a;
    asm("{ .reg .u64 t; cvta.to.shared.u64 t, %1; cvt.u32.u64 %0, t; }"
        : "=r"(a) : "l"(p));
    return a;
}
__device__ __forceinline__ uint32_t pack_bf16(float lo, float hi) {
    uint32_t r;
    asm("cvt.rn.bf16x2.f32 %0, %1, %2;" : "=r"(r) : "f"(hi), "f"(lo));
    return r;
}
__device__ __forceinline__ void ldsm_x4(uint32_t* r, uint32_t addr) {
    asm volatile("ldmatrix.sync.aligned.m8n8.x4.shared.b16 {%0,%1,%2,%3}, [%4];"
        : "=r"(r[0]), "=r"(r[1]), "=r"(r[2]), "=r"(r[3]) : "r"(addr));
}
__device__ __forceinline__ void ldsm_x4_t(uint32_t* r, uint32_t addr) {
    asm volatile("ldmatrix.sync.aligned.m8n8.x4.trans.shared.b16 {%0,%1,%2,%3}, [%4];"
        : "=r"(r[0]), "=r"(r[1]), "=r"(r[2]), "=r"(r[3]) : "r"(addr));
}
__device__ __forceinline__ void mma_bf16(float* c, const uint32_t* a, const uint32_t* b) {
    asm volatile(
        "mma.sync.aligned.m16n8k16.row.col.f32.bf16.bf16.f32 "
        "{%0,%1,%2,%3}, {%4,%5,%6,%7}, {%8,%9}, {%0,%1,%2,%3};"
        : "+f"(c[0]), "+f"(c[1]), "+f"(c[2]), "+f"(c[3])
        : "r"(a[0]), "r"(a[1]), "r"(a[2]), "r"(a[3]), "r"(b[0]), "r"(b[1]));
}
#define CP_ASYNC16(dst, src) \
    asm volatile("cp.async.cg.shared.global [%0], [%1], 16;" \
                 :: "r"(dst), "l"(src) : "memory")
#define CP_COMMIT() asm volatile("cp.async.commit_group;" ::: "memory")
#define CP_WAIT2()  asm volatile("cp.async.wait_group 2;" ::: "memory")
#define CP_WAIT0()  asm volatile("cp.async.wait_group 0;" ::: "memory")

// ============================================================================
// Fused fp32 -> bf16 conversion for x, y, WQ, WK, WV, WZ in ONE launch.
// ============================================================================
#define N4BIG (TOTAL_ELEMS / 4)
#define N4W   ((CC * CC) / 4)
#define N4TOT (2 * N4BIG + 4 * N4W)

__global__ void cvt_all_kernel(const float4* __restrict__ x,
                               const float4* __restrict__ y,
                               const float4* __restrict__ wq,
                               const float4* __restrict__ wk,
                               const float4* __restrict__ wv,
                               const float4* __restrict__ wz,
                               uint2* __restrict__ xb,
                               uint2* __restrict__ yb,
                               uint2* __restrict__ wb)
{
    int i = blockIdx.x * blockDim.x + threadIdx.x;
    const int stride = gridDim.x * blockDim.x;
    for (; i < N4TOT; i += stride) {
        const float4* src;
        uint2* dst;
        int idx;
        if (i < N4BIG)            { src = x;  dst = xb; idx = i; }
        else if (i < 2 * N4BIG)   { src = y;  dst = yb; idx = i - N4BIG; }
        else {
            const int j = i - 2 * N4BIG;
            const int w = j / N4W;
            idx = j - w * N4W;
            src = (w == 0) ? wq : (w == 1) ? wk : (w == 2) ? wv : wz;
            dst = wb + (size_t)w * N4W;
        }
        float4 v = src[idx];
        dst[idx] = make_uint2(pack_bf16(v.x, v.y), pack_bf16(v.z, v.w));
    }
}

// ============================================================================
// GEMM core config (validated R15/R16)
// ============================================================================
#define PA 20
#define PBW 68
#define A_STG (128 * PA)                     // 2560 words
#define B_STG (32 * PBW)                     // 2176 words
#define STG (A_STG + B_STG)                  // 4736 words = 18944 B
#define NSTAGE 4
#define CA_SMEM (NSTAGE * STG * 4)           // 75776 B

// ---- mainloop macro body shared by both GEMM kernels ----
// (expanded inline in each kernel to avoid pointer/flag overhead)

// ============================================================================
// Merged Q/K/V GEMM: one launch, grid (2, 98, 24); z = b*3 + w, w in {Q,K,V}.
// K(b) and V(b) adjacent in z -> y tile L2 reuse. bf16 out.
// ============================================================================
__global__ void __launch_bounds__(256, 2)
gemm_qkv_kernel(const __nv_bfloat16* __restrict__ Wb4,   // 4*CC*CC, use w*CC*CC
                const __nv_bfloat16* __restrict__ xb,
                const __nv_bfloat16* __restrict__ yb,
                uint32_t* __restrict__ oQ,
                uint32_t* __restrict__ oK,
                uint32_t* __restrict__ oV)
{
    extern __shared__ uint32_t smu[];
    const uint32_t smb = smem_u32(smu);

    const int tid  = threadIdx.x;
    const int wid  = tid >> 5;
    const int lane = tid & 31;
    const int g    = lane >> 2;
    const int t    = lane & 3;
    const int wm   = (wid >> 2) * 64;
    const int wn   = (wid & 3) * 32;

    const int m0 = blockIdx.x * 128;
    const int n0 = blockIdx.y * 128;
    const int w  = blockIdx.z % 3;
    const int b  = blockIdx.z / 3;

    const __nv_bfloat16* Wb  = Wb4 + (size_t)w * CC * CC;
    const __nv_bfloat16* inb = ((w == 0) ? xb : yb) + (size_t)b * ELEMS_PER_IMG;
    uint32_t* ob = ((w == 0) ? oQ : (w == 1) ? oK : oV)
                 + (size_t)b * (ELEMS_PER_IMG / 2);

    const uint32_t aoff = ((wm + (lane & 15)) * PA + ((lane >> 4) << 2)) * 4;
    const uint32_t boff = ((((lane & 7) + ((lane >> 3) & 1) * 8) * PBW)
                           + ((lane >> 4) << 2)) * 4;

    float acc[4][4][4];
#pragma unroll
    for (int f = 0; f < 4; f++)
#pragma unroll
        for (int j = 0; j < 4; j++)
#pragma unroll
            for (int e = 0; e < 4; e++) acc[f][j][e] = 0.0f;

    auto issue_chunk = [&](int kk, int s) {
        const uint32_t base = smb + (uint32_t)s * (STG * 4);
#pragma unroll
        for (int it = 0; it < 2; ++it) {
            const int f = tid + it * 256;
            const int ar = f >> 2, ac = f & 3;
            const __nv_bfloat16* asrc = Wb + (size_t)(m0 + ar) * CC + kk + ac * 8;
            CP_ASYNC16(base + (uint32_t)(ar * PA + ac * 4) * 4, asrc);
            const int bk = f >> 4, bn = f & 15;
            const __nv_bfloat16* bsrc = inb + (size_t)(kk + bk) * HWSZ + n0 + bn * 8;
            CP_ASYNC16(base + (uint32_t)(A_STG * 4) + (uint32_t)(bk * PBW + bn * 4) * 4, bsrc);
        }
        CP_COMMIT();
    };

    issue_chunk(0, 0);
    issue_chunk(32, 1);
    issue_chunk(64, 2);

    for (int i = 0; i < 8; ++i) {
        CP_WAIT2();
        __syncthreads();

        if (i < 5) issue_chunk((i + 3) * 32, (i + 3) & 3);
        else       CP_COMMIT();

        const int s = i & 3;
        const uint32_t aA = smb + (uint32_t)s * (STG * 4) + aoff;
        const uint32_t aB = smb + (uint32_t)s * (STG * 4) + A_STG * 4 + boff
                          + (wn >> 1) * 4;
#pragma unroll
        for (int ks = 0; ks < 2; ++ks) {
            uint32_t afr[4][4];
#pragma unroll
            for (int f = 0; f < 4; ++f)
                ldsm_x4(afr[f], aA + f * (16 * PA * 4) + ks * 32);
#pragma unroll
            for (int j2 = 0; j2 < 2; ++j2) {
                uint32_t bfr[4];
                ldsm_x4_t(bfr, aB + j2 * 32 + ks * (16 * PBW * 4));
#pragma unroll
                for (int f = 0; f < 4; ++f) {
                    mma_bf16(acc[f][2 * j2],     afr[f], bfr);
                    mma_bf16(acc[f][2 * j2 + 1], afr[f], bfr + 2);
                }
            }
        }
    }

#pragma unroll
    for (int f = 0; f < 4; ++f) {
#pragma unroll
        for (int j = 0; j < 4; ++j) {
            const int row = m0 + wm + f * 16 + g;
            const int col = n0 + wn + j * 8 + 2 * t;   // even
            ob[((size_t)row * HWSZ + col) >> 1]       = pack_bf16(acc[f][j][0], acc[f][j][1]);
            ob[((size_t)(row + 8) * HWSZ + col) >> 1] = pack_bf16(acc[f][j][2], acc[f][j][3]);
        }
    }
}

// ============================================================================
// Final GEMM: bf16 in (Z), fp32 out with residual + relu (unchanged R15/R16).
// ============================================================================
__global__ void __launch_bounds__(256, 2)
gemm_fin_kernel(const __nv_bfloat16* __restrict__ Wb,
                const __nv_bfloat16* __restrict__ inb0,
                const float* __restrict__ res,
                float* __restrict__ outp)
{
    extern __shared__ uint32_t smu[];
    const uint32_t smb = smem_u32(smu);

    const int tid  = threadIdx.x;
    const int wid  = tid >> 5;
    const int lane = tid & 31;
    const int g    = lane >> 2;
    const int t    = lane & 3;
    const int wm   = (wid >> 2) * 64;
    const int wn   = (wid & 3) * 32;

    const int m0 = blockIdx.x * 128;
    const int n0 = blockIdx.y * 128;
    const int b  = blockIdx.z;
    const __nv_bfloat16* inb = inb0 + (size_t)b * ELEMS_PER_IMG;

    const uint32_t aoff = ((wm + (lane & 15)) * PA + ((lane >> 4) << 2)) * 4;
    const uint32_t boff = ((((lane & 7) + ((lane >> 3) & 1) * 8) * PBW)
                           + ((lane >> 4) << 2)) * 4;

    float acc[4][4][4];
#pragma unroll
    for (int f = 0; f < 4; f++)
#pragma unroll
        for (int j = 0; j < 4; j++)
#pragma unroll
            for (int e = 0; e < 4; e++) acc[f][j][e] = 0.0f;

    auto issue_chunk = [&](int kk, int s) {
        const uint32_t base = smb + (uint32_t)s * (STG * 4);
#pragma unroll
        for (int it = 0; it < 2; ++it) {
            const int f = tid + it * 256;
            const int ar = f >> 2, ac = f & 3;
            const __nv_bfloat16* asrc = Wb + (size_t)(m0 + ar) * CC + kk + ac * 8;
            CP_ASYNC16(base + (uint32_t)(ar * PA + ac * 4) * 4, asrc);
            const int bk = f >> 4, bn = f & 15;
            const __nv_bfloat16* bsrc = inb + (size_t)(kk + bk) * HWSZ + n0 + bn * 8;
            CP_ASYNC16(base + (uint32_t)(A_STG * 4) + (uint32_t)(bk * PBW + bn * 4) * 4, bsrc);
        }
        CP_COMMIT();
    };

    issue_chunk(0, 0);
    issue_chunk(32, 1);
    issue_chunk(64, 2);

    for (int i = 0; i < 8; ++i) {
        CP_WAIT2();
        __syncthreads();

        if (i < 5) issue_chunk((i + 3) * 32, (i + 3) & 3);
        else       CP_COMMIT();

        const int s = i & 3;
        const uint32_t aA = smb + (uint32_t)s * (STG * 4) + aoff;
        const uint32_t aB = smb + (uint32_t)s * (STG * 4) + A_STG * 4 + boff
                          + (wn >> 1) * 4;
#pragma unroll
        for (int ks = 0; ks < 2; ++ks) {
            uint32_t afr[4][4];
#pragma unroll
            for (int f = 0; f < 4; ++f)
                ldsm_x4(afr[f], aA + f * (16 * PA * 4) + ks * 32);
#pragma unroll
            for (int j2 = 0; j2 < 2; ++j2) {
                uint32_t bfr[4];
                ldsm_x4_t(bfr, aB + j2 * 32 + ks * (16 * PBW * 4));
#pragma unroll
                for (int f = 0; f < 4; ++f) {
                    mma_bf16(acc[f][2 * j2],     afr[f], bfr);
                    mma_bf16(acc[f][2 * j2 + 1], afr[f], bfr + 2);
                }
            }
        }
    }

    float* outb = outp + (size_t)b * ELEMS_PER_IMG;
    const float* resb = res + (size_t)b * ELEMS_PER_IMG;
#pragma unroll
    for (int f = 0; f < 4; ++f) {
#pragma unroll
        for (int j = 0; j < 4; ++j) {
            const int row = m0 + wm + f * 16 + g;
            const int col = n0 + wn + j * 8 + 2 * t;
            float2 v0 = { acc[f][j][0], acc[f][j][1] };
            float2 v1 = { acc[f][j][2], acc[f][j][3] };
            float2 r0 = *reinterpret_cast<const float2*>(&resb[(size_t)row * HWSZ + col]);
            float2 r1 = *reinterpret_cast<const float2*>(&resb[(size_t)(row + 8) * HWSZ + col]);
            v0.x = fmaxf(v0.x + r0.x, 0.0f);
            v0.y = fmaxf(v0.y + r0.y, 0.0f);
            v1.x = fmaxf(v1.x + r1.x, 0.0f);
            v1.y = fmaxf(v1.y + r1.y, 0.0f);
            *reinterpret_cast<float2*>(&outb[(size_t)row * HWSZ + col]) = v0;
            *reinterpret_cast<float2*>(&outb[(size_t)(row + 8) * HWSZ + col]) = v1;
        }
    }
}

// ============================================================================
// bf16 tensor-core attention per (b,c). NEW: M kept in registers — the S
// C-fragment maps exactly onto the A-fragment needed for Z=M@V:
//   a = { pack(acc[2ks][0..1]), pack(acc[2ks][2..3]),
//         pack(acc[2ks+1][0..1]), pack(acc[2ks+1][2..3]) }
// No smem round-trip, no syncwarp, identical packed bf16 values.
// ============================================================================
#define PTQ 60
#define ATSZ (HH * PTQ)                 // 6720 words
#define ATTN_SMEM (3 * ATSZ * 4)        // 80640 B

__global__ void __launch_bounds__(224, 2)
attn_tc_kernel(const __nv_bfloat16* __restrict__ Qg,
               const __nv_bfloat16* __restrict__ Kg,
               const __nv_bfloat16* __restrict__ Vg,
               uint32_t* __restrict__ Z)
{
    extern __shared__ uint32_t smu[];
    const uint32_t smb = smem_u32(smu);
    const uint32_t kbase = smb;
    const uint32_t vbase = smb + ATSZ * 4;
    const uint32_t qbase = smb + 2 * ATSZ * 4;

    const size_t ebase = (size_t)blockIdx.x * HWSZ;
    const int tid  = threadIdx.x;
    const int wid  = tid >> 5;
    const int lane = tid & 31;
    const int g    = lane >> 2;
    const int t    = lane & 3;
    const int r0   = wid * 16;

    // ---- cp.async staging ----
    {
        const __nv_bfloat16* Qb = Qg + ebase;
        const __nv_bfloat16* Kb = Kg + ebase;
        const __nv_bfloat16* Vb = Vg + ebase;
        for (int i = tid; i < HH * 14; i += 224) {
            const int row = i / 14, c = i % 14;
            const uint32_t so = (uint32_t)(row * PTQ + c * 4) * 4;
            const size_t   go = (size_t)row * HH + c * 8;
            CP_ASYNC16(qbase + so, Qb + go);
            CP_ASYNC16(kbase + so, Kb + go);
            CP_ASYNC16(vbase + so, Vb + go);
        }
        CP_COMMIT();
        CP_WAIT0();
    }
    __syncthreads();

    const uint32_t aoff = ((r0 + (lane & 15)) * PTQ + ((lane >> 4) << 2)) * 4;
    const uint32_t boff = ((((lane & 7) + ((lane >> 3) & 1) * 8) * PTQ)
                           + ((lane >> 4) << 2)) * 4;

    float acc[14][4];
#pragma unroll
    for (int j = 0; j < 14; j++)
#pragma unroll
        for (int e = 0; e < 4; e++) acc[j][e] = 0.0f;

    // ---- S = Q @ K ----
#pragma unroll
    for (int ks = 0; ks < 7; ++ks) {
        uint32_t a[4];
        ldsm_x4(a, qbase + aoff + ks * 32);
#pragma unroll
        for (int j2 = 0; j2 < 7; ++j2) {
            uint32_t bfr[4];
            ldsm_x4_t(bfr, kbase + boff + j2 * 32 + ks * (16 * PTQ * 4));
            mma_bf16(acc[2 * j2],     a, bfr);
            mma_bf16(acc[2 * j2 + 1], a, bfr + 2);
        }
    }

    // ---- softmax ----
    {
        float mx0 = -1e30f, mx1 = -1e30f;
#pragma unroll
        for (int j = 0; j < 14; ++j) {
            mx0 = fmaxf(mx0, fmaxf(acc[j][0], acc[j][1]));
            mx1 = fmaxf(mx1, fmaxf(acc[j][2], acc[j][3]));
        }
        mx0 = fmaxf(mx0, __shfl_xor_sync(0xffffffffu, mx0, 1));
        mx0 = fmaxf(mx0, __shfl_xor_sync(0xffffffffu, mx0, 2));
        mx1 = fmaxf(mx1, __shfl_xor_sync(0xffffffffu, mx1, 1));
        mx1 = fmaxf(mx1, __shfl_xor_sync(0xffffffffu, mx1, 2));
        float s0 = 0.0f, s1 = 0.0f;
#pragma unroll
        for (int j = 0; j < 14; ++j) {
            acc[j][0] = __expf(acc[j][0] - mx0);
            acc[j][1] = __expf(acc[j][1] - mx0);
            acc[j][2] = __expf(acc[j][2] - mx1);
            acc[j][3] = __expf(acc[j][3] - mx1);
            s0 += acc[j][0] + acc[j][1];
            s1 += acc[j][2] + acc[j][3];
        }
        s0 += __shfl_xor_sync(0xffffffffu, s0, 1);
        s0 += __shfl_xor_sync(0xffffffffu, s0, 2);
        s1 += __shfl_xor_sync(0xffffffffu, s1, 1);
        s1 += __shfl_xor_sync(0xffffffffu, s1, 2);
        const float i0 = 1.0f / s0, i1 = 1.0f / s1;
#pragma unroll
        for (int j = 0; j < 14; ++j) {
            acc[j][0] *= i0; acc[j][1] *= i0;
            acc[j][2] *= i1; acc[j][3] *= i1;
        }
    }

    // ---- M -> register A-fragments (no smem round-trip) ----
    uint32_t mreg[7][4];
#pragma unroll
    for (int ks = 0; ks < 7; ++ks) {
        mreg[ks][0] = pack_bf16(acc[2 * ks][0],     acc[2 * ks][1]);
        mreg[ks][1] = pack_bf16(acc[2 * ks][2],     acc[2 * ks][3]);
        mreg[ks][2] = pack_bf16(acc[2 * ks + 1][0], acc[2 * ks + 1][1]);
        mreg[ks][3] = pack_bf16(acc[2 * ks + 1][2], acc[2 * ks + 1][3]);
    }

    // ---- Z = M @ V (A from regs, B via trans-ldsm) ----
#pragma unroll
    for (int j = 0; j < 14; j++)
#pragma unroll
        for (int e = 0; e < 4; e++) acc[j][e] = 0.0f;

#pragma unroll
    for (int ks = 0; ks < 7; ++ks) {
#pragma unroll
        for (int j2 = 0; j2 < 7; ++j2) {
            uint32_t bfr[4];
            ldsm_x4_t(bfr, vbase + boff + j2 * 32 + ks * (16 * PTQ * 4));
            mma_bf16(acc[2 * j2],     mreg[ks], bfr);
            mma_bf16(acc[2 * j2 + 1], mreg[ks], bfr + 2);
        }
    }

    // ---- store Z as packed bf16 words ----
    uint32_t* Zb = Z + ebase / 2;
#pragma unroll
    for (int j = 0; j < 14; ++j) {
        const int col = j * 8 + 2 * t;   // even
        Zb[((r0 + g) * HH + col) >> 1]     = pack_bf16(acc[j][0], acc[j][1]);
        Zb[((r0 + g + 8) * HH + col) >> 1] = pack_bf16(acc[j][2], acc[j][3]);
    }
}

extern "C" void kernel_launch(void* const* d_in, const int* in_sizes, int n_in,
                              void* d_out, int out_size)
{
    const float* x  = (const float*)d_in[0];
    const float* y  = (const float*)d_in[1];
    const float* WQ = (const float*)d_in[2];
    const float* WK = (const float*)d_in[3];
    const float* WV = (const float*)d_in[4];
    const float* WZ = (const float*)d_in[5];
    float* out = (float*)d_out;

    void *dQ, *dK, *dV, *dZ, *dxb, *dyb, *dWb;
    cudaGetSymbolAddress(&dQ, g_Q);
    cudaGetSymbolAddress(&dK, g_K);
    cudaGetSymbolAddress(&dV, g_V);
    cudaGetSymbolAddress(&dZ, g_Zs);
    cudaGetSymbolAddress(&dxb, g_xb);
    cudaGetSymbolAddress(&dyb, g_yb);
    cudaGetSymbolAddress(&dWb, g_Wb);

    cudaFuncSetAttribute(attn_tc_kernel, cudaFuncAttributeMaxDynamicSharedMemorySize,
                         ATTN_SMEM);
    cudaFuncSetAttribute(gemm_qkv_kernel,
                         cudaFuncAttributeMaxDynamicSharedMemorySize, CA_SMEM);
    cudaFuncSetAttribute(gemm_fin_kernel,
                         cudaFuncAttributeMaxDynamicSharedMemorySize, CA_SMEM);

    __nv_bfloat16* xb = (__nv_bfloat16*)dxb;
    __nv_bfloat16* yb = (__nv_bfloat16*)dyb;
    __nv_bfloat16* Wb = (__nv_bfloat16*)dWb;

    // ---- prep: ONE fused fp32 -> bf16 conversion launch ----
    cvt_all_kernel<<<2368, 256>>>((const float4*)x, (const float4*)y,
                                  (const float4*)WQ, (const float4*)WK,
                                  (const float4*)WV, (const float4*)WZ,
                                  (uint2*)xb, (uint2*)yb, (uint2*)Wb);

    // ---- merged Q/K/V GEMM: one launch, 24 jobs ----
    dim3 gqkv(2, HWSZ / 128, 3 * BB);
    gemm_qkv_kernel<<<gqkv, 256, CA_SMEM>>>(Wb, xb, yb,
                                            (uint32_t*)dQ, (uint32_t*)dK,
                                            (uint32_t*)dV);

    attn_tc_kernel<<<BB * CC, 224, ATTN_SMEM>>>((const __nv_bfloat16*)dQ,
                                                (const __nv_bfloat16*)dK,
                                                (const __nv_bfloat16*)dV,
                                                (uint32_t*)dZ);

    dim3 gfin(2, HWSZ / 128, BB);
    gemm_fin_kernel<<<gfin, 256, CA_SMEM>>>(Wb + 3 * CC * CC,
                                            (const __nv_bfloat16*)dZ, x, out);
}